// round 1
// baseline (speedup 1.0000x reference)
#include <cuda_runtime.h>
#include <cstdint>

// Problem constants
constexpr int B_ = 4;
constexpr int T_ = 2048;
constexpr int C_ = 1024;
constexpr int H_ = 16;
constexpr int HD = 64;          // head dim
constexpr int BH = B_ * H_;     // 64
constexpr int M_ROWS = B_ * T_; // 8192
constexpr int N_QKV = 3 * C_;   // 3072

constexpr float SCALE = -1.0f / 16.0f; // -1/(2*sqrt(64))

// Device scratch (static allocation — no cudaMalloc allowed)
__device__ float g_q[BH * T_ * HD];
__device__ float g_k[BH * T_ * HD];
__device__ float g_v[BH * T_ * HD];
__device__ float g_y[M_ROWS * C_];
__device__ float g_q2[BH * T_];
__device__ float g_k2[BH * T_];

// ---------------------------------------------------------------------------
// SGEMM: C = A(MxK) * B(KxN) + bias, 128x128 block tile, 8x8 per thread.
// MODE 0: A = x, epilogue scatters into g_q/g_k/g_v (qkv layout transform)
// MODE 1: A = g_y (device symbol), epilogue writes plain row-major to Cout
// Requires M%128==0, N%128==0, K%8==0 (true for all our shapes).
// ---------------------------------------------------------------------------
template <int MODE>
__global__ __launch_bounds__(256) void sgemm_kernel(
    const float* __restrict__ A_in, const float* __restrict__ Bm,
    const float* __restrict__ bias, float* __restrict__ Cout,
    int M, int N, int K)
{
    __shared__ float As[8][128];
    __shared__ float Bs[8][128];

    const float* __restrict__ A = (MODE == 1) ? g_y : A_in;

    const int tid = threadIdx.x;
    const int m0 = blockIdx.y * 128;
    const int n0 = blockIdx.x * 128;

    const int aRow = tid >> 1;          // 0..127
    const int aCol = (tid & 1) * 4;     // 0 or 4
    const int bRow = tid >> 5;          // 0..7
    const int bCol = (tid & 31) * 4;    // 0..124

    const int ty = tid >> 4;
    const int tx = tid & 15;
    const int r0 = ty * 8;
    const int c0 = tx * 8;

    float acc[8][8];
#pragma unroll
    for (int i = 0; i < 8; i++)
#pragma unroll
        for (int j = 0; j < 8; j++) acc[i][j] = 0.0f;

    for (int k0 = 0; k0 < K; k0 += 8) {
        float4 av = *(const float4*)&A[(size_t)(m0 + aRow) * K + k0 + aCol];
        float4 bv = *(const float4*)&Bm[(size_t)(k0 + bRow) * N + n0 + bCol];
        __syncthreads(); // previous tile fully consumed
        As[aCol + 0][aRow] = av.x;
        As[aCol + 1][aRow] = av.y;
        As[aCol + 2][aRow] = av.z;
        As[aCol + 3][aRow] = av.w;
        *(float4*)&Bs[bRow][bCol] = bv;
        __syncthreads();

#pragma unroll
        for (int kk = 0; kk < 8; kk++) {
            float a_reg[8], b_reg[8];
            *(float4*)&a_reg[0] = *(const float4*)&As[kk][r0];
            *(float4*)&a_reg[4] = *(const float4*)&As[kk][r0 + 4];
            *(float4*)&b_reg[0] = *(const float4*)&Bs[kk][c0];
            *(float4*)&b_reg[4] = *(const float4*)&Bs[kk][c0 + 4];
#pragma unroll
            for (int i = 0; i < 8; i++)
#pragma unroll
                for (int j = 0; j < 8; j++)
                    acc[i][j] += a_reg[i] * b_reg[j];
        }
    }

    // Epilogue
#pragma unroll
    for (int i = 0; i < 8; i++) {
        const int m = m0 + r0 + i;
#pragma unroll
        for (int j = 0; j < 8; j++) {
            const int n = n0 + c0 + j;
            float v = acc[i][j] + bias[n];
            if (MODE == 0) {
                // n in [0,3072): part (q/k/v), head, dim; m = b*T + t
                const int part = n >> 10;
                const int cc = n & 1023;
                const int h = cc >> 6;
                const int d = cc & 63;
                const int b = m >> 11;
                const int t = m & 2047;
                float* dst = (part == 0) ? g_q : (part == 1) ? g_k : g_v;
                dst[(((size_t)(b * H_ + h) * T_) + t) * HD + d] = v;
            } else {
                Cout[(size_t)m * N + n] = v;
            }
        }
    }
}

// ---------------------------------------------------------------------------
// Row squared norms of q and k
// ---------------------------------------------------------------------------
__global__ void q2k2_kernel() {
    const int idx = blockIdx.x * blockDim.x + threadIdx.x;
    if (idx >= BH * T_) return;
    const float4* q = (const float4*)(g_q + (size_t)idx * HD);
    const float4* k = (const float4*)(g_k + (size_t)idx * HD);
    float sq = 0.0f, sk = 0.0f;
#pragma unroll
    for (int i = 0; i < HD / 4; i++) {
        float4 a = q[i];
        sq += a.x * a.x + a.y * a.y + a.z * a.z + a.w * a.w;
        float4 b = k[i];
        sk += b.x * b.x + b.y * b.y + b.z * b.z + b.w * b.w;
    }
    g_q2[idx] = sq;
    g_k2[idx] = sk;
}

// ---------------------------------------------------------------------------
// Streaming causal Gaussian-kernel attention (no softmax normalization ->
// no running max/sum; just accumulate Y += S_tile @ V_tile).
// grid = (T/64 q-tiles, BH), block = 256 (16x16 threads, 4x4 microtile)
// Dynamic smem layout:
//   Qst [64][68]  (d-major, padded)     17408 B
//   KV  [64*68]   K as [d*68+c], later V as [c*64+d]   17408 B
//   Ss  [64][64]  (row-major)           16384 B        total 51200 B
// ---------------------------------------------------------------------------
constexpr int ATTN_SMEM = (64 * 68 + 64 * 68 + 64 * 64) * 4;

__global__ __launch_bounds__(256) void attn_kernel() {
    extern __shared__ float sm[];
    float* Qst = sm;              // [d*68 + r]
    float* KV = sm + 64 * 68;     // K: [d*68 + c];  V: [c*64 + d]
    float* Ss = KV + 64 * 68;     // [r*64 + c]

    const int bh = blockIdx.y;
    const int qt = blockIdx.x;
    const int tid = threadIdx.x;
    const int ty = tid >> 4;
    const int tx = tid & 15;
    const int r0 = ty * 4;
    const int c0 = tx * 4;  // also d0 in the PV phase
    const int q0 = qt * 64;

    const float* __restrict__ qp = g_q + (size_t)bh * T_ * HD;
    const float* __restrict__ kp = g_k + (size_t)bh * T_ * HD;
    const float* __restrict__ vp = g_v + (size_t)bh * T_ * HD;

    // Load Q tile transposed (coalesced global read, padded smem store)
    for (int i = tid; i < 64 * 64; i += 256) {
        const int r = i >> 6, d = i & 63;
        Qst[d * 68 + r] = qp[(size_t)(q0 + r) * HD + d];
    }

    float q2r[4];
#pragma unroll
    for (int i = 0; i < 4; i++)
        q2r[i] = g_q2[bh * T_ + q0 + r0 + i];

    float yacc[4][4];
#pragma unroll
    for (int i = 0; i < 4; i++)
#pragma unroll
        for (int j = 0; j < 4; j++) yacc[i][j] = 0.0f;

    for (int jt = 0; jt <= qt; jt++) {
        const int k0 = jt * 64;

        __syncthreads(); // previous PV reads of KV/Ss done
        for (int i = tid; i < 64 * 64; i += 256) {
            const int c = i >> 6, d = i & 63;
            KV[d * 68 + c] = kp[(size_t)(k0 + c) * HD + d];
        }
        __syncthreads();

        // S = Q . K^T  (4x4 microtile)
        float sacc[4][4];
#pragma unroll
        for (int i = 0; i < 4; i++)
#pragma unroll
            for (int j = 0; j < 4; j++) sacc[i][j] = 0.0f;

#pragma unroll 8
        for (int kk = 0; kk < 64; kk++) {
            float4 qv = *(const float4*)&Qst[kk * 68 + r0];
            float4 kv = *(const float4*)&KV[kk * 68 + c0];
            const float qa[4] = {qv.x, qv.y, qv.z, qv.w};
            const float ka[4] = {kv.x, kv.y, kv.z, kv.w};
#pragma unroll
            for (int i = 0; i < 4; i++)
#pragma unroll
                for (int j = 0; j < 4; j++)
                    sacc[i][j] += qa[i] * ka[j];
        }

        // exp + causal mask -> Ss
        float k2c[4];
#pragma unroll
        for (int j = 0; j < 4; j++)
            k2c[j] = g_k2[bh * T_ + k0 + c0 + j];

#pragma unroll
        for (int i = 0; i < 4; i++) {
            const int tq = q0 + r0 + i;
#pragma unroll
            for (int j = 0; j < 4; j++) {
                const int tk = k0 + c0 + j;
                float val = 0.0f;
                if (tk <= tq) {
                    const float sq = q2r[i] + k2c[j] - 2.0f * sacc[i][j];
                    val = __expf(sq * SCALE);
                }
                Ss[(r0 + i) * 64 + (c0 + j)] = val;
            }
        }
        __syncthreads(); // S complete, all K reads done

        // Load V tile (natural layout) over the K buffer
        for (int i = tid; i < 64 * 64; i += 256) {
            const int c = i >> 6, d = i & 63;
            KV[c * 64 + d] = vp[(size_t)(k0 + c) * HD + d];
        }
        __syncthreads();

        // Y += S @ V
#pragma unroll 16
        for (int c = 0; c < 64; c++) {
            float4 vv = *(const float4*)&KV[c * 64 + c0];
            const float va[4] = {vv.x, vv.y, vv.z, vv.w};
            float s0 = Ss[(r0 + 0) * 64 + c];
            float s1 = Ss[(r0 + 1) * 64 + c];
            float s2 = Ss[(r0 + 2) * 64 + c];
            float s3 = Ss[(r0 + 3) * 64 + c];
#pragma unroll
            for (int j = 0; j < 4; j++) {
                yacc[0][j] += s0 * va[j];
                yacc[1][j] += s1 * va[j];
                yacc[2][j] += s2 * va[j];
                yacc[3][j] += s3 * va[j];
            }
        }
    }

    // Write back to (B,T,C) layout: y[b][t][h*64+d]
    const int b = bh >> 4;
    const int h = bh & 15;
#pragma unroll
    for (int i = 0; i < 4; i++) {
        const int t = q0 + r0 + i;
        float4 o = make_float4(yacc[i][0], yacc[i][1], yacc[i][2], yacc[i][3]);
        *(float4*)&g_y[((size_t)(b * T_ + t)) * C_ + h * HD + c0] = o;
    }
}

// ---------------------------------------------------------------------------
extern "C" void kernel_launch(void* const* d_in, const int* in_sizes, int n_in,
                              void* d_out, int out_size) {
    (void)in_sizes; (void)n_in; (void)out_size;
    const float* x      = (const float*)d_in[0];
    const float* W_attn = (const float*)d_in[1];
    const float* b_attn = (const float*)d_in[2];
    const float* W_proj = (const float*)d_in[3];
    const float* b_proj = (const float*)d_in[4];
    float* out = (float*)d_out;

    // 1) QKV GEMM with layout-transform epilogue
    dim3 g1(N_QKV / 128, M_ROWS / 128);
    sgemm_kernel<0><<<g1, 256>>>(x, W_attn, b_attn, nullptr, M_ROWS, N_QKV, C_);

    // 2) row norms
    q2k2_kernel<<<(BH * T_ + 255) / 256, 256>>>();

    // 3) streaming causal attention
    cudaFuncSetAttribute(attn_kernel, cudaFuncAttributeMaxDynamicSharedMemorySize,
                         ATTN_SMEM);
    attn_kernel<<<dim3(T_ / 64, BH), 256, ATTN_SMEM>>>();

    // 4) output projection
    dim3 g2(C_ / 128, M_ROWS / 128);
    sgemm_kernel<1><<<g2, 256>>>(nullptr, W_proj, b_proj, out, M_ROWS, C_, C_);
}

// round 2
// speedup vs baseline: 2.1573x; 2.1573x over previous
#include <cuda_runtime.h>
#include <cstdint>

// Problem constants
constexpr int B_ = 4;
constexpr int T_ = 2048;
constexpr int C_ = 1024;
constexpr int H_ = 16;
constexpr int HD = 64;
constexpr int BH = B_ * H_;     // 64
constexpr int M_ROWS = B_ * T_; // 8192
constexpr int N_QKV = 3 * C_;   // 3072

constexpr float SCALE = -1.0f / 16.0f; // -1/(2*sqrt(64))

// Device scratch (no cudaMalloc allowed)
__device__ float g_q[BH * T_ * HD];
__device__ float g_k[BH * T_ * HD];
__device__ float g_v[BH * T_ * HD];
__device__ float g_y[M_ROWS * C_];
__device__ float g_q2[BH * T_];
__device__ float g_k2[BH * T_];

__device__ __forceinline__ uint32_t f2tf32(float x) {
    uint32_t r;
    asm("cvt.rna.tf32.f32 %0, %1;" : "=r"(r) : "f"(x));
    return r;
}

__device__ __forceinline__ void mma_tf32(float& c0, float& c1, float& c2, float& c3,
                                         uint32_t a0, uint32_t a1, uint32_t a2, uint32_t a3,
                                         uint32_t b0, uint32_t b1) {
    asm volatile(
        "mma.sync.aligned.m16n8k8.row.col.f32.tf32.tf32.f32 "
        "{%0,%1,%2,%3}, {%4,%5,%6,%7}, {%8,%9}, {%0,%1,%2,%3};"
        : "+f"(c0), "+f"(c1), "+f"(c2), "+f"(c3)
        : "r"(a0), "r"(a1), "r"(a2), "r"(a3), "r"(b0), "r"(b1));
}

// ---------------------------------------------------------------------------
// Dense tf32 GEMM: C = A(MxK) * B(KxN) + bias.
// 128x128x16 block tile, 256 threads = 8 warps (4 in M x 2 in N), warp 32x64.
// MODE 0: A = x, epilogue scatters into g_q/g_k/g_v.
// MODE 1: A = g_y, epilogue writes row-major to Cout.
// ---------------------------------------------------------------------------
template <int MODE>
__global__ __launch_bounds__(256) void gemm_tf32(
    const float* __restrict__ A_in, const float* __restrict__ Bm,
    const float* __restrict__ bias, float* __restrict__ Cout,
    int M, int N, int K)
{
    constexpr int BK = 16;
    __shared__ uint32_t As[BK][128 + 4]; // [k][m]
    __shared__ uint32_t Bs[BK][128 + 4]; // [k][n]

    const float* __restrict__ A = (MODE == 1) ? g_y : A_in;

    const int tid = threadIdx.x;
    const int lane = tid & 31;
    const int wid = tid >> 5;
    const int g = lane >> 2;
    const int t4 = lane & 3;
    const int wm = (wid & 3) * 32;
    const int wn = (wid >> 2) * 64;
    const int m0 = blockIdx.y * 128;
    const int n0 = blockIdx.x * 128;

    const int arow = tid >> 2;        // 0..63 (+64)
    const int acol = (tid & 3) * 4;   // 0..12
    const int brow = tid >> 5;        // 0..7 (+8)
    const int bcol = (lane) * 4;      // 0..124

    float acc[2][8][4] = {};

    for (int k0 = 0; k0 < K; k0 += BK) {
        float4 a0 = *(const float4*)&A[(size_t)(m0 + arow) * K + k0 + acol];
        float4 a1 = *(const float4*)&A[(size_t)(m0 + arow + 64) * K + k0 + acol];
        float4 b0 = *(const float4*)&Bm[(size_t)(k0 + brow) * N + n0 + bcol];
        float4 b1 = *(const float4*)&Bm[(size_t)(k0 + brow + 8) * N + n0 + bcol];
        __syncthreads();
        As[acol + 0][arow] = f2tf32(a0.x);
        As[acol + 1][arow] = f2tf32(a0.y);
        As[acol + 2][arow] = f2tf32(a0.z);
        As[acol + 3][arow] = f2tf32(a0.w);
        As[acol + 0][arow + 64] = f2tf32(a1.x);
        As[acol + 1][arow + 64] = f2tf32(a1.y);
        As[acol + 2][arow + 64] = f2tf32(a1.z);
        As[acol + 3][arow + 64] = f2tf32(a1.w);
        {
            uint4 u0 = make_uint4(f2tf32(b0.x), f2tf32(b0.y), f2tf32(b0.z), f2tf32(b0.w));
            uint4 u1 = make_uint4(f2tf32(b1.x), f2tf32(b1.y), f2tf32(b1.z), f2tf32(b1.w));
            *(uint4*)&Bs[brow][bcol] = u0;
            *(uint4*)&Bs[brow + 8][bcol] = u1;
        }
        __syncthreads();

#pragma unroll
        for (int kk = 0; kk < BK; kk += 8) {
            uint32_t af[2][4];
#pragma unroll
            for (int mi = 0; mi < 2; mi++) {
                const int mb = wm + mi * 16;
                af[mi][0] = As[kk + t4][mb + g];
                af[mi][1] = As[kk + t4][mb + g + 8];
                af[mi][2] = As[kk + t4 + 4][mb + g];
                af[mi][3] = As[kk + t4 + 4][mb + g + 8];
            }
            uint32_t bf[8][2];
#pragma unroll
            for (int ni = 0; ni < 8; ni++) {
                const int nb = wn + ni * 8 + g;
                bf[ni][0] = Bs[kk + t4][nb];
                bf[ni][1] = Bs[kk + t4 + 4][nb];
            }
#pragma unroll
            for (int mi = 0; mi < 2; mi++)
#pragma unroll
                for (int ni = 0; ni < 8; ni++)
                    mma_tf32(acc[mi][ni][0], acc[mi][ni][1], acc[mi][ni][2], acc[mi][ni][3],
                             af[mi][0], af[mi][1], af[mi][2], af[mi][3],
                             bf[ni][0], bf[ni][1]);
        }
    }

    // Epilogue
#pragma unroll
    for (int mi = 0; mi < 2; mi++) {
#pragma unroll
        for (int ni = 0; ni < 8; ni++) {
            const int r0 = m0 + wm + mi * 16 + g;
            const int r1 = r0 + 8;
            const int c0 = n0 + wn + ni * 8 + 2 * t4;
            const float bia = bias[c0];
            const float bib = bias[c0 + 1];
            float v00 = acc[mi][ni][0] + bia;
            float v01 = acc[mi][ni][1] + bib;
            float v10 = acc[mi][ni][2] + bia;
            float v11 = acc[mi][ni][3] + bib;
            if (MODE == 0) {
#pragma unroll
                for (int e = 0; e < 4; e++) {
                    const int m = (e < 2) ? r0 : r1;
                    const int n = c0 + (e & 1);
                    const float v = (e == 0) ? v00 : (e == 1) ? v01 : (e == 2) ? v10 : v11;
                    const int part = n >> 10;
                    const int cc = n & 1023;
                    const int h = cc >> 6;
                    const int d = cc & 63;
                    const int b = m >> 11;
                    const int t = m & 2047;
                    float* dst = (part == 0) ? g_q : (part == 1) ? g_k : g_v;
                    dst[(((size_t)(b * H_ + h) * T_) + t) * HD + d] = v;
                }
            } else {
                *(float2*)&Cout[(size_t)r0 * N + c0] = make_float2(v00, v01);
                *(float2*)&Cout[(size_t)r1 * N + c0] = make_float2(v10, v11);
            }
        }
    }
}

// ---------------------------------------------------------------------------
// Row squared norms of q and k
// ---------------------------------------------------------------------------
__global__ void q2k2_kernel() {
    const int idx = blockIdx.x * blockDim.x + threadIdx.x;
    if (idx >= BH * T_) return;
    const float4* q = (const float4*)(g_q + (size_t)idx * HD);
    const float4* k = (const float4*)(g_k + (size_t)idx * HD);
    float sq = 0.0f, sk = 0.0f;
#pragma unroll
    for (int i = 0; i < HD / 4; i++) {
        float4 a = q[i];
        sq += a.x * a.x + a.y * a.y + a.z * a.z + a.w * a.w;
        float4 b = k[i];
        sk += b.x * b.x + b.y * b.y + b.z * b.z + b.w * b.w;
    }
    g_q2[idx] = sq;
    g_k2[idx] = sk;
}

// ---------------------------------------------------------------------------
// Streaming causal Gaussian attention with tf32 mma.
// Block = (bh, 64-row q tile), 256 threads = 8 warps (2 in M x 4 in N).
// Warp S/Y tile = 32x16. No softmax state needed (unnormalized kernel scores).
// Dynamic smem (uint32 words):
//   Qs [64 d][68]   (d-major, tf32)
//   Ks [64 d][68]   (d-major, tf32)
//   Vs [64 t][68]   (token-major, tf32)
//   Ss [64 t][68]   (token-major = k-major for SV mma, tf32)
//   q2s[64], k2s[64] (float)
// ---------------------------------------------------------------------------
constexpr int ATT_Q = 0;
constexpr int ATT_K = 64 * 68;
constexpr int ATT_V = 2 * 64 * 68;
constexpr int ATT_S = 3 * 64 * 68;
constexpr int ATT_N = 4 * 64 * 68;
constexpr int ATTN_SMEM = (4 * 64 * 68 + 128) * 4;

__global__ __launch_bounds__(256) void attn_tf32() {
    extern __shared__ uint32_t sm[];
    uint32_t* Qs = sm + ATT_Q;
    uint32_t* Ks = sm + ATT_K;
    uint32_t* Vs = sm + ATT_V;
    uint32_t* Ss = sm + ATT_S;
    float* q2s = (float*)(sm + ATT_N);
    float* k2s = q2s + 64;

    const int bh = blockIdx.y;
    const int qt = blockIdx.x;
    const int q0 = qt * 64;
    const int tid = threadIdx.x;
    const int lane = tid & 31;
    const int wid = tid >> 5;
    const int g = lane >> 2;
    const int t4 = lane & 3;
    const int wm = (wid & 1) * 32;   // q rows
    const int wn = (wid >> 1) * 16;  // k cols / d cols

    const float* __restrict__ qp = g_q + (size_t)bh * T_ * HD;
    const float* __restrict__ kp = g_k + (size_t)bh * T_ * HD;
    const float* __restrict__ vp = g_v + (size_t)bh * T_ * HD;

    const int ltok = tid >> 4;           // 0..15 (+16,+32,+48)
    const int ld4 = (tid & 15) * 4;      // 0..60

    // Load Q tile (transpose to d-major) + q2
#pragma unroll
    for (int bb = 0; bb < 4; bb++) {
        const int t = ltok + bb * 16;
        float4 v = *(const float4*)&qp[(size_t)(q0 + t) * HD + ld4];
        Qs[(ld4 + 0) * 68 + t] = f2tf32(v.x);
        Qs[(ld4 + 1) * 68 + t] = f2tf32(v.y);
        Qs[(ld4 + 2) * 68 + t] = f2tf32(v.z);
        Qs[(ld4 + 3) * 68 + t] = f2tf32(v.w);
    }
    if (tid < 64) q2s[tid] = g_q2[bh * T_ + q0 + tid];

    float yacc[2][2][4] = {};

    for (int jt = 0; jt <= qt; jt++) {
        const int k0 = jt * 64;
        __syncthreads(); // previous iteration's SV reads complete
#pragma unroll
        for (int bb = 0; bb < 4; bb++) {
            const int t = ltok + bb * 16;
            float4 kv = *(const float4*)&kp[(size_t)(k0 + t) * HD + ld4];
            Ks[(ld4 + 0) * 68 + t] = f2tf32(kv.x);
            Ks[(ld4 + 1) * 68 + t] = f2tf32(kv.y);
            Ks[(ld4 + 2) * 68 + t] = f2tf32(kv.z);
            Ks[(ld4 + 3) * 68 + t] = f2tf32(kv.w);
            float4 vv = *(const float4*)&vp[(size_t)(k0 + t) * HD + ld4];
            *(uint4*)&Vs[t * 68 + ld4] =
                make_uint4(f2tf32(vv.x), f2tf32(vv.y), f2tf32(vv.z), f2tf32(vv.w));
        }
        if (tid < 64) k2s[tid] = g_k2[bh * T_ + k0 + tid];
        __syncthreads();

        // S = Q . K^T
        float sacc[2][2][4] = {};
#pragma unroll
        for (int kk = 0; kk < 64; kk += 8) {
            uint32_t af[2][4];
#pragma unroll
            for (int mi = 0; mi < 2; mi++) {
                const int mb = wm + mi * 16;
                af[mi][0] = Qs[(kk + t4) * 68 + mb + g];
                af[mi][1] = Qs[(kk + t4) * 68 + mb + g + 8];
                af[mi][2] = Qs[(kk + t4 + 4) * 68 + mb + g];
                af[mi][3] = Qs[(kk + t4 + 4) * 68 + mb + g + 8];
            }
#pragma unroll
            for (int ni = 0; ni < 2; ni++) {
                const int nb = wn + ni * 8 + g;
                uint32_t b0 = Ks[(kk + t4) * 68 + nb];
                uint32_t b1 = Ks[(kk + t4 + 4) * 68 + nb];
#pragma unroll
                for (int mi = 0; mi < 2; mi++)
                    mma_tf32(sacc[mi][ni][0], sacc[mi][ni][1], sacc[mi][ni][2], sacc[mi][ni][3],
                             af[mi][0], af[mi][1], af[mi][2], af[mi][3], b0, b1);
            }
        }

        // exp + causal mask in registers, store S (tf32) token-major
        const bool diag = (jt == qt);
#pragma unroll
        for (int mi = 0; mi < 2; mi++) {
#pragma unroll
            for (int ni = 0; ni < 2; ni++) {
                const int r0l = wm + mi * 16 + g;
                const int r1l = r0l + 8;
                const int c0l = wn + ni * 8 + 2 * t4;
                const int c1l = c0l + 1;
                const float q2a = q2s[r0l], q2b = q2s[r1l];
                const float k2a = k2s[c0l], k2b = k2s[c1l];
                float e00 = __expf((q2a + k2a - 2.0f * sacc[mi][ni][0]) * SCALE);
                float e01 = __expf((q2a + k2b - 2.0f * sacc[mi][ni][1]) * SCALE);
                float e10 = __expf((q2b + k2a - 2.0f * sacc[mi][ni][2]) * SCALE);
                float e11 = __expf((q2b + k2b - 2.0f * sacc[mi][ni][3]) * SCALE);
                if (diag) {
                    if (c0l > r0l) e00 = 0.0f;
                    if (c1l > r0l) e01 = 0.0f;
                    if (c0l > r1l) e10 = 0.0f;
                    if (c1l > r1l) e11 = 0.0f;
                }
                Ss[c0l * 68 + r0l] = f2tf32(e00);
                Ss[c1l * 68 + r0l] = f2tf32(e01);
                Ss[c0l * 68 + r1l] = f2tf32(e10);
                Ss[c1l * 68 + r1l] = f2tf32(e11);
            }
        }
        __syncthreads();

        // Y += S @ V
#pragma unroll
        for (int kk = 0; kk < 64; kk += 8) {
            uint32_t af[2][4];
#pragma unroll
            for (int mi = 0; mi < 2; mi++) {
                const int mb = wm + mi * 16;
                af[mi][0] = Ss[(kk + t4) * 68 + mb + g];
                af[mi][1] = Ss[(kk + t4) * 68 + mb + g + 8];
                af[mi][2] = Ss[(kk + t4 + 4) * 68 + mb + g];
                af[mi][3] = Ss[(kk + t4 + 4) * 68 + mb + g + 8];
            }
#pragma unroll
            for (int ni = 0; ni < 2; ni++) {
                const int nb = wn + ni * 8 + g;
                uint32_t b0 = Vs[(kk + t4) * 68 + nb];
                uint32_t b1 = Vs[(kk + t4 + 4) * 68 + nb];
#pragma unroll
                for (int mi = 0; mi < 2; mi++)
                    mma_tf32(yacc[mi][ni][0], yacc[mi][ni][1], yacc[mi][ni][2], yacc[mi][ni][3],
                             af[mi][0], af[mi][1], af[mi][2], af[mi][3], b0, b1);
            }
        }
    }

    // Write Y to (B,T,C) layout
    const int b = bh >> 4;
    const int h = bh & 15;
#pragma unroll
    for (int mi = 0; mi < 2; mi++) {
#pragma unroll
        for (int ni = 0; ni < 2; ni++) {
            const int t0 = q0 + wm + mi * 16 + g;
            const int t1 = t0 + 8;
            const int d = wn + ni * 8 + 2 * t4;
            *(float2*)&g_y[((size_t)(b * T_ + t0)) * C_ + h * HD + d] =
                make_float2(yacc[mi][ni][0], yacc[mi][ni][1]);
            *(float2*)&g_y[((size_t)(b * T_ + t1)) * C_ + h * HD + d] =
                make_float2(yacc[mi][ni][2], yacc[mi][ni][3]);
        }
    }
}

// ---------------------------------------------------------------------------
extern "C" void kernel_launch(void* const* d_in, const int* in_sizes, int n_in,
                              void* d_out, int out_size) {
    (void)in_sizes; (void)n_in; (void)out_size;
    const float* x      = (const float*)d_in[0];
    const float* W_attn = (const float*)d_in[1];
    const float* b_attn = (const float*)d_in[2];
    const float* W_proj = (const float*)d_in[3];
    const float* b_proj = (const float*)d_in[4];
    float* out = (float*)d_out;

    dim3 g1(N_QKV / 128, M_ROWS / 128);
    gemm_tf32<0><<<g1, 256>>>(x, W_attn, b_attn, nullptr, M_ROWS, N_QKV, C_);

    q2k2_kernel<<<(BH * T_ + 255) / 256, 256>>>();

    cudaFuncSetAttribute(attn_tf32, cudaFuncAttributeMaxDynamicSharedMemorySize,
                         ATTN_SMEM);
    attn_tf32<<<dim3(T_ / 64, BH), 256, ATTN_SMEM>>>();

    dim3 g2(C_ / 128, M_ROWS / 128);
    gemm_tf32<1><<<g2, 256>>>(nullptr, W_proj, b_proj, out, M_ROWS, C_, C_);
}

// round 5
// speedup vs baseline: 3.4075x; 1.5795x over previous
#include <cuda_runtime.h>
#include <cstdint>

// Problem constants
constexpr int B_ = 4;
constexpr int T_ = 2048;
constexpr int C_ = 1024;
constexpr int H_ = 16;
constexpr int HD = 64;
constexpr int BH = B_ * H_;     // 64
constexpr int M_ROWS = B_ * T_; // 8192
constexpr int N_QKV = 3 * C_;   // 3072

constexpr float SCALE = -1.0f / 16.0f; // -1/(2*sqrt(64))

// Device scratch (no cudaMalloc allowed)
__device__ float g_q[BH * T_ * HD];
__device__ float g_k[BH * T_ * HD];
__device__ float g_v[BH * T_ * HD];
__device__ float g_y[M_ROWS * C_];
__device__ float g_q2[BH * T_];
__device__ float g_k2[BH * T_];
__device__ float g_xr[M_ROWS * C_];   // tf32-rounded x
__device__ float g_wa[C_ * N_QKV];    // tf32-rounded W_attn
__device__ float g_wp[C_ * C_];       // tf32-rounded W_proj

__device__ __forceinline__ uint32_t f2tf32(float x) {
    uint32_t r;
    asm("cvt.rna.tf32.f32 %0, %1;" : "=r"(r) : "f"(x));
    return r;
}
__device__ __forceinline__ float roundtf(float x) {
    return __uint_as_float(f2tf32(x));
}

__device__ __forceinline__ void mma_tf32(float& c0, float& c1, float& c2, float& c3,
                                         uint32_t a0, uint32_t a1, uint32_t a2, uint32_t a3,
                                         uint32_t b0, uint32_t b1) {
    asm volatile(
        "mma.sync.aligned.m16n8k8.row.col.f32.tf32.tf32.f32 "
        "{%0,%1,%2,%3}, {%4,%5,%6,%7}, {%8,%9}, {%0,%1,%2,%3};"
        : "+f"(c0), "+f"(c1), "+f"(c2), "+f"(c3)
        : "r"(a0), "r"(a1), "r"(a2), "r"(a3), "r"(b0), "r"(b1));
}

__device__ __forceinline__ void cp_async16(uint32_t dst, const void* src) {
    asm volatile("cp.async.cg.shared.global [%0], [%1], 16;" :: "r"(dst), "l"(src));
}
__device__ __forceinline__ void cp_commit() {
    asm volatile("cp.async.commit_group;");
}
template <int N>
__device__ __forceinline__ void cp_wait() {
    asm volatile("cp.async.wait_group %0;" :: "n"(N));
}
__device__ __forceinline__ uint32_t smem_u32(const void* p) {
    return (uint32_t)__cvta_generic_to_shared(p);
}

// ---------------------------------------------------------------------------
// Pre-round x, W_attn, W_proj to tf32-exact fp32 (so mma truncation is exact).
// ---------------------------------------------------------------------------
constexpr size_t X4 = (size_t)M_ROWS * C_ / 4;
constexpr size_t WA4 = (size_t)C_ * N_QKV / 4;
constexpr size_t WP4 = (size_t)C_ * C_ / 4;

__global__ void prep_round(const float* __restrict__ x,
                           const float* __restrict__ wa,
                           const float* __restrict__ wp) {
    size_t i = (size_t)blockIdx.x * blockDim.x + threadIdx.x;
    const float4* src;
    float4* dst;
    size_t off;
    if (i < X4) { src = (const float4*)x; dst = (float4*)g_xr; off = i; }
    else if (i < X4 + WA4) { src = (const float4*)wa; dst = (float4*)g_wa; off = i - X4; }
    else if (i < X4 + WA4 + WP4) { src = (const float4*)wp; dst = (float4*)g_wp; off = i - X4 - WA4; }
    else return;
    float4 v = src[off];
    v.x = roundtf(v.x); v.y = roundtf(v.y); v.z = roundtf(v.z); v.w = roundtf(v.w);
    dst[off] = v;
}

// ---------------------------------------------------------------------------
// Dense tf32 GEMM, 128x128x16 tile, 3-stage cp.async pipeline, 256 threads.
// MODE 0: A=g_xr, B=g_wa, epilogue scatters tf32-rounded q/k/v.
// MODE 1: A=g_y,  B=g_wp, epilogue writes fp32 row-major to Cout.
// ---------------------------------------------------------------------------
constexpr int APAD = 20, BPAD = 136;
constexpr int ASZ = 128 * APAD, BSZ = 16 * BPAD;
constexpr int GSTG = ASZ + BSZ; // words per stage
constexpr int GEMM_SMEM = 3 * GSTG * 4;

template <int MODE>
__global__ __launch_bounds__(256) void gemm_tf32(
    const float* __restrict__ bias, float* __restrict__ Cout,
    int M, int N, int K)
{
    extern __shared__ float sm[];

    const float* __restrict__ A = (MODE == 0) ? g_xr : g_y;
    const float* __restrict__ Bm = (MODE == 0) ? g_wa : g_wp;

    const int tid = threadIdx.x;
    const int lane = tid & 31;
    const int wid = tid >> 5;
    const int g = lane >> 2;
    const int t4 = lane & 3;
    const int wm = (wid & 3) * 32;
    const int wn = (wid >> 2) * 64;
    const int m0 = blockIdx.y * 128;
    const int n0 = blockIdx.x * 128;

    const int nt = K >> 4;

    auto issue = [&](int stage, int k0) {
        float* sA = sm + stage * GSTG;
        float* sB = sA + ASZ;
        // A tile: 128 rows x 16 cols = 512 16B-chunks, 2 per thread
#pragma unroll
        for (int h = 0; h < 2; h++) {
            int c = tid + h * 256;
            int m = c >> 2, kc = (c & 3) * 4;
            cp_async16(smem_u32(&sA[m * APAD + kc]),
                       &A[(size_t)(m0 + m) * K + k0 + kc]);
        }
        // B tile: 16 rows x 128 cols = 512 16B-chunks, 2 per thread
#pragma unroll
        for (int h = 0; h < 2; h++) {
            int c = tid + h * 256;
            int kr = c >> 5, nc = (c & 31) * 4;
            cp_async16(smem_u32(&sB[kr * BPAD + nc]),
                       &Bm[(size_t)(k0 + kr) * N + n0 + nc]);
        }
        cp_commit();
    };

    float acc[2][8][4] = {};

    issue(0, 0);
    issue(1, 16);

    for (int i = 0; i < nt; i++) {
        // Outstanding groups before wait: {i, i+1} for i<=nt-2, only {i} at tail.
        if (i == nt - 1) cp_wait<0>(); else cp_wait<1>();
        __syncthreads();
        if (i + 2 < nt) issue((i + 2) % 3, (i + 2) * 16);

        const float* sA = sm + (i % 3) * GSTG;
        const float* sB = sA + ASZ;

#pragma unroll
        for (int kk = 0; kk < 16; kk += 8) {
            uint32_t af[2][4];
#pragma unroll
            for (int mi = 0; mi < 2; mi++) {
                const int mb = wm + mi * 16 + g;
                af[mi][0] = __float_as_uint(sA[(mb) * APAD + kk + t4]);
                af[mi][1] = __float_as_uint(sA[(mb + 8) * APAD + kk + t4]);
                af[mi][2] = __float_as_uint(sA[(mb) * APAD + kk + t4 + 4]);
                af[mi][3] = __float_as_uint(sA[(mb + 8) * APAD + kk + t4 + 4]);
            }
            uint32_t bf[8][2];
#pragma unroll
            for (int ni = 0; ni < 8; ni++) {
                const int nb = wn + ni * 8 + g;
                bf[ni][0] = __float_as_uint(sB[(kk + t4) * BPAD + nb]);
                bf[ni][1] = __float_as_uint(sB[(kk + t4 + 4) * BPAD + nb]);
            }
#pragma unroll
            for (int mi = 0; mi < 2; mi++)
#pragma unroll
                for (int ni = 0; ni < 8; ni++)
                    mma_tf32(acc[mi][ni][0], acc[mi][ni][1], acc[mi][ni][2], acc[mi][ni][3],
                             af[mi][0], af[mi][1], af[mi][2], af[mi][3],
                             bf[ni][0], bf[ni][1]);
        }
    }

    // Epilogue
#pragma unroll
    for (int mi = 0; mi < 2; mi++) {
#pragma unroll
        for (int ni = 0; ni < 8; ni++) {
            const int r0 = m0 + wm + mi * 16 + g;
            const int r1 = r0 + 8;
            const int c0 = n0 + wn + ni * 8 + 2 * t4;
            const float bia = bias[c0];
            const float bib = bias[c0 + 1];
            float v00 = acc[mi][ni][0] + bia;
            float v01 = acc[mi][ni][1] + bib;
            float v10 = acc[mi][ni][2] + bia;
            float v11 = acc[mi][ni][3] + bib;
            if (MODE == 0) {
#pragma unroll
                for (int e = 0; e < 4; e++) {
                    const int m = (e < 2) ? r0 : r1;
                    const int n = c0 + (e & 1);
                    float v = (e == 0) ? v00 : (e == 1) ? v01 : (e == 2) ? v10 : v11;
                    v = roundtf(v); // q,k,v stored tf32-exact
                    const int part = n >> 10;
                    const int cc = n & 1023;
                    const int h = cc >> 6;
                    const int d = cc & 63;
                    const int b = m >> 11;
                    const int t = m & 2047;
                    float* dst = (part == 0) ? g_q : (part == 1) ? g_k : g_v;
                    dst[(((size_t)(b * H_ + h) * T_) + t) * HD + d] = v;
                }
            } else {
                *(float2*)&Cout[(size_t)r0 * N + c0] = make_float2(v00, v01);
                *(float2*)&Cout[(size_t)r1 * N + c0] = make_float2(v10, v11);
            }
        }
    }
}

// ---------------------------------------------------------------------------
// Row squared norms of q and k (inputs already tf32-rounded)
// ---------------------------------------------------------------------------
__global__ void q2k2_kernel() {
    const int idx = blockIdx.x * blockDim.x + threadIdx.x;
    if (idx >= BH * T_) return;
    const float4* q = (const float4*)(g_q + (size_t)idx * HD);
    const float4* k = (const float4*)(g_k + (size_t)idx * HD);
    float sq = 0.0f, sk = 0.0f;
#pragma unroll
    for (int i = 0; i < HD / 4; i++) {
        float4 a = q[i];
        sq += a.x * a.x + a.y * a.y + a.z * a.z + a.w * a.w;
        float4 b = k[i];
        sk += b.x * b.x + b.y * b.y + b.z * b.z + b.w * b.w;
    }
    g_q2[idx] = sq;
    g_k2[idx] = sk;
}

// ---------------------------------------------------------------------------
// Streaming causal Gaussian attention, tf32 mma, 2-stage cp.async K/V.
// Block=(q-tile 64, bh), 256 thr = 8 warps (2 M x 4 N), warp 32x16.
// Natural [token][dim] layouts. Pads: Q/K/S 68, V 72.
// ---------------------------------------------------------------------------
constexpr int QPAD = 68, VPAD = 72;
constexpr int Q_OFF = 0;
constexpr int S_OFF = 64 * QPAD;
constexpr int K_OFF = 2 * 64 * QPAD;            // 2 stages of 64*68
constexpr int V_OFF = K_OFF + 2 * 64 * QPAD;    // 2 stages of 64*72
constexpr int ATTN_SMEM = (V_OFF + 2 * 64 * VPAD) * 4;

__global__ __launch_bounds__(256) void attn_tf32() {
    extern __shared__ float sm[];
    float* Qs = sm + Q_OFF;
    float* Ss = sm + S_OFF;

    const int bh = blockIdx.y;
    const int qt = blockIdx.x;
    const int q0 = qt * 64;
    const int tid = threadIdx.x;
    const int lane = tid & 31;
    const int wid = tid >> 5;
    const int g = lane >> 2;
    const int t4 = lane & 3;
    const int wm = (wid & 1) * 32;   // q rows
    const int wn = (wid >> 1) * 16;  // k cols / d cols

    const float* __restrict__ qp = g_q + (size_t)bh * T_ * HD;
    const float* __restrict__ kp = g_k + (size_t)bh * T_ * HD;
    const float* __restrict__ vp = g_v + (size_t)bh * T_ * HD;

    // Full 64x64 tile = 1024 16B-chunks -> 4 chunks per thread (K and V each).
    auto issueKV = [&](int stage, int k0) {
        float* Ks = sm + K_OFF + stage * 64 * QPAD;
        float* Vs = sm + V_OFF + stage * 64 * VPAD;
#pragma unroll
        for (int h = 0; h < 4; h++) {
            int c = tid + h * 256;
            int row = c >> 4, d4 = (c & 15) * 4;
            cp_async16(smem_u32(&Ks[row * QPAD + d4]), &kp[(size_t)(k0 + row) * HD + d4]);
            cp_async16(smem_u32(&Vs[row * VPAD + d4]), &vp[(size_t)(k0 + row) * HD + d4]);
        }
        cp_commit();
    };

    // Prologue: Q tile + first K/V stage in one group
    {
#pragma unroll
        for (int h = 0; h < 4; h++) {
            int c = tid + h * 256;
            int row = c >> 4, d4 = (c & 15) * 4;
            cp_async16(smem_u32(&Qs[row * QPAD + d4]), &qp[(size_t)(q0 + row) * HD + d4]);
        }
        issueKV(0, 0);
    }

    // q2 in registers
    float q2v[4];
#pragma unroll
    for (int mi = 0; mi < 2; mi++) {
        q2v[mi * 2 + 0] = g_q2[bh * T_ + q0 + wm + mi * 16 + g];
        q2v[mi * 2 + 1] = g_q2[bh * T_ + q0 + wm + mi * 16 + g + 8];
    }

    float yacc[2][2][4] = {};

    for (int jt = 0; jt <= qt; jt++) {
        const int st = jt & 1;
        cp_wait<0>();     // full drain: stage st ready
        __syncthreads();  // prev SV reads of Ss/KV done across block
        if (jt < qt) issueKV(st ^ 1, (jt + 1) * 64);

        // k2 for this tile (LDG latency covered by QK mma below)
        float2 k20 = *(const float2*)&g_k2[bh * T_ + jt * 64 + wn + 2 * t4];
        float2 k21 = *(const float2*)&g_k2[bh * T_ + jt * 64 + wn + 8 + 2 * t4];

        const float* Ks = sm + K_OFF + st * 64 * QPAD;
        const float* Vs = sm + V_OFF + st * 64 * VPAD;

        // S = Q . K^T
        float sacc[2][2][4] = {};
#pragma unroll
        for (int kk = 0; kk < 64; kk += 8) {
            uint32_t af[2][4];
#pragma unroll
            for (int mi = 0; mi < 2; mi++) {
                const int mb = wm + mi * 16 + g;
                af[mi][0] = __float_as_uint(Qs[(mb) * QPAD + kk + t4]);
                af[mi][1] = __float_as_uint(Qs[(mb + 8) * QPAD + kk + t4]);
                af[mi][2] = __float_as_uint(Qs[(mb) * QPAD + kk + t4 + 4]);
                af[mi][3] = __float_as_uint(Qs[(mb + 8) * QPAD + kk + t4 + 4]);
            }
#pragma unroll
            for (int ni = 0; ni < 2; ni++) {
                const int nb = wn + ni * 8 + g;
                uint32_t b0 = __float_as_uint(Ks[(nb) * QPAD + kk + t4]);
                uint32_t b1 = __float_as_uint(Ks[(nb) * QPAD + kk + t4 + 4]);
#pragma unroll
                for (int mi = 0; mi < 2; mi++)
                    mma_tf32(sacc[mi][ni][0], sacc[mi][ni][1], sacc[mi][ni][2], sacc[mi][ni][3],
                             af[mi][0], af[mi][1], af[mi][2], af[mi][3], b0, b1);
            }
        }

        // exp + causal mask, store S (tf32-rounded) row-major
        const bool diag = (jt == qt);
#pragma unroll
        for (int mi = 0; mi < 2; mi++) {
#pragma unroll
            for (int ni = 0; ni < 2; ni++) {
                const int r0l = wm + mi * 16 + g;
                const int r1l = r0l + 8;
                const int c0l = wn + ni * 8 + 2 * t4;
                const int c1l = c0l + 1;
                const float k2a = (ni == 0) ? k20.x : k21.x;
                const float k2b = (ni == 0) ? k20.y : k21.y;
                const float q2a = q2v[mi * 2 + 0];
                const float q2b = q2v[mi * 2 + 1];
                float e00 = __expf((q2a + k2a - 2.0f * sacc[mi][ni][0]) * SCALE);
                float e01 = __expf((q2a + k2b - 2.0f * sacc[mi][ni][1]) * SCALE);
                float e10 = __expf((q2b + k2a - 2.0f * sacc[mi][ni][2]) * SCALE);
                float e11 = __expf((q2b + k2b - 2.0f * sacc[mi][ni][3]) * SCALE);
                if (diag) {
                    if (c0l > r0l) e00 = 0.0f;
                    if (c1l > r0l) e01 = 0.0f;
                    if (c0l > r1l) e10 = 0.0f;
                    if (c1l > r1l) e11 = 0.0f;
                }
                *(float2*)&Ss[r0l * QPAD + c0l] = make_float2(roundtf(e00), roundtf(e01));
                *(float2*)&Ss[r1l * QPAD + c0l] = make_float2(roundtf(e10), roundtf(e11));
            }
        }
        __syncthreads();  // S complete

        // Y += S @ V
#pragma unroll
        for (int kk = 0; kk < 64; kk += 8) {
            uint32_t af[2][4];
#pragma unroll
            for (int mi = 0; mi < 2; mi++) {
                const int mb = wm + mi * 16 + g;
                af[mi][0] = __float_as_uint(Ss[(mb) * QPAD + kk + t4]);
                af[mi][1] = __float_as_uint(Ss[(mb + 8) * QPAD + kk + t4]);
                af[mi][2] = __float_as_uint(Ss[(mb) * QPAD + kk + t4 + 4]);
                af[mi][3] = __float_as_uint(Ss[(mb + 8) * QPAD + kk + t4 + 4]);
            }
#pragma unroll
            for (int ni = 0; ni < 2; ni++) {
                const int nb = wn + ni * 8 + g;
                uint32_t b0 = __float_as_uint(Vs[(kk + t4) * VPAD + nb]);
                uint32_t b1 = __float_as_uint(Vs[(kk + t4 + 4) * VPAD + nb]);
#pragma unroll
                for (int mi = 0; mi < 2; mi++)
                    mma_tf32(yacc[mi][ni][0], yacc[mi][ni][1], yacc[mi][ni][2], yacc[mi][ni][3],
                             af[mi][0], af[mi][1], af[mi][2], af[mi][3], b0, b1);
            }
        }
    }

    // Write Y (tf32-rounded, consumed by proj mma) to (B,T,C)
    const int b = bh >> 4;
    const int h = bh & 15;
#pragma unroll
    for (int mi = 0; mi < 2; mi++) {
#pragma unroll
        for (int ni = 0; ni < 2; ni++) {
            const int t0 = q0 + wm + mi * 16 + g;
            const int t1 = t0 + 8;
            const int d = wn + ni * 8 + 2 * t4;
            *(float2*)&g_y[((size_t)(b * T_ + t0)) * C_ + h * HD + d] =
                make_float2(roundtf(yacc[mi][ni][0]), roundtf(yacc[mi][ni][1]));
            *(float2*)&g_y[((size_t)(b * T_ + t1)) * C_ + h * HD + d] =
                make_float2(roundtf(yacc[mi][ni][2]), roundtf(yacc[mi][ni][3]));
        }
    }
}

// ---------------------------------------------------------------------------
extern "C" void kernel_launch(void* const* d_in, const int* in_sizes, int n_in,
                              void* d_out, int out_size) {
    (void)in_sizes; (void)n_in; (void)out_size;
    const float* x      = (const float*)d_in[0];
    const float* W_attn = (const float*)d_in[1];
    const float* b_attn = (const float*)d_in[2];
    const float* W_proj = (const float*)d_in[3];
    const float* b_proj = (const float*)d_in[4];
    float* out = (float*)d_out;

    cudaFuncSetAttribute(gemm_tf32<0>, cudaFuncAttributeMaxDynamicSharedMemorySize, GEMM_SMEM);
    cudaFuncSetAttribute(gemm_tf32<1>, cudaFuncAttributeMaxDynamicSharedMemorySize, GEMM_SMEM);
    cudaFuncSetAttribute(attn_tf32, cudaFuncAttributeMaxDynamicSharedMemorySize, ATTN_SMEM);

    const size_t total4 = X4 + WA4 + WP4;
    prep_round<<<(unsigned)((total4 + 255) / 256), 256>>>(x, W_attn, W_proj);

    dim3 g1(N_QKV / 128, M_ROWS / 128);
    gemm_tf32<0><<<g1, 256, GEMM_SMEM>>>(b_attn, nullptr, M_ROWS, N_QKV, C_);

    q2k2_kernel<<<(BH * T_ + 255) / 256, 256>>>();

    attn_tf32<<<dim3(T_ / 64, BH), 256, ATTN_SMEM>>>();

    dim3 g2(C_ / 128, M_ROWS / 128);
    gemm_tf32<1><<<g2, 256, GEMM_SMEM>>>(b_proj, out, M_ROWS, C_, C_);
}

// round 6
// speedup vs baseline: 3.4530x; 1.0133x over previous
#include <cuda_runtime.h>
#include <cstdint>

// Problem constants
constexpr int B_ = 4;
constexpr int T_ = 2048;
constexpr int C_ = 1024;
constexpr int H_ = 16;
constexpr int HD = 64;
constexpr int BH = B_ * H_;     // 64
constexpr int M_ROWS = B_ * T_; // 8192
constexpr int N_QKV = 3 * C_;   // 3072

constexpr float SCALE = -1.0f / 16.0f; // -1/(2*sqrt(64))

// Device scratch (no cudaMalloc allowed)
__device__ float g_q[BH * T_ * HD];
__device__ float g_k[BH * T_ * HD];
__device__ float g_v[BH * T_ * HD];
__device__ float g_y[M_ROWS * C_];
__device__ float g_q2[BH * T_];
__device__ float g_k2[BH * T_];
__device__ float g_xr[M_ROWS * C_];   // tf32-rounded x
__device__ float g_wa[C_ * N_QKV];    // tf32-rounded W_attn
__device__ float g_wp[C_ * C_];       // tf32-rounded W_proj

__device__ __forceinline__ uint32_t f2tf32(float x) {
    uint32_t r;
    asm("cvt.rna.tf32.f32 %0, %1;" : "=r"(r) : "f"(x));
    return r;
}
__device__ __forceinline__ float roundtf(float x) {
    return __uint_as_float(f2tf32(x));
}

__device__ __forceinline__ void mma_tf32(float& c0, float& c1, float& c2, float& c3,
                                         uint32_t a0, uint32_t a1, uint32_t a2, uint32_t a3,
                                         uint32_t b0, uint32_t b1) {
    asm volatile(
        "mma.sync.aligned.m16n8k8.row.col.f32.tf32.tf32.f32 "
        "{%0,%1,%2,%3}, {%4,%5,%6,%7}, {%8,%9}, {%0,%1,%2,%3};"
        : "+f"(c0), "+f"(c1), "+f"(c2), "+f"(c3)
        : "r"(a0), "r"(a1), "r"(a2), "r"(a3), "r"(b0), "r"(b1));
}

__device__ __forceinline__ void cp_async16(uint32_t dst, const void* src) {
    asm volatile("cp.async.cg.shared.global [%0], [%1], 16;" :: "r"(dst), "l"(src));
}
__device__ __forceinline__ void cp_commit() {
    asm volatile("cp.async.commit_group;");
}
template <int N>
__device__ __forceinline__ void cp_wait() {
    asm volatile("cp.async.wait_group %0;" :: "n"(N));
}
__device__ __forceinline__ uint32_t smem_u32(const void* p) {
    return (uint32_t)__cvta_generic_to_shared(p);
}

// ---------------------------------------------------------------------------
// Pre-round x, W_attn, W_proj to tf32-exact fp32 (so mma truncation is exact).
// ---------------------------------------------------------------------------
constexpr size_t X4 = (size_t)M_ROWS * C_ / 4;
constexpr size_t WA4 = (size_t)C_ * N_QKV / 4;
constexpr size_t WP4 = (size_t)C_ * C_ / 4;

__global__ void prep_round(const float* __restrict__ x,
                           const float* __restrict__ wa,
                           const float* __restrict__ wp) {
    size_t i = (size_t)blockIdx.x * blockDim.x + threadIdx.x;
    const float4* src;
    float4* dst;
    size_t off;
    if (i < X4) { src = (const float4*)x; dst = (float4*)g_xr; off = i; }
    else if (i < X4 + WA4) { src = (const float4*)wa; dst = (float4*)g_wa; off = i - X4; }
    else if (i < X4 + WA4 + WP4) { src = (const float4*)wp; dst = (float4*)g_wp; off = i - X4 - WA4; }
    else return;
    float4 v = src[off];
    v.x = roundtf(v.x); v.y = roundtf(v.y); v.z = roundtf(v.z); v.w = roundtf(v.w);
    dst[off] = v;
}

// ---------------------------------------------------------------------------
// Dense tf32 GEMM, 128x128x16 tile, 3-stage cp.async pipeline, 256 threads.
// MODE 0: A=g_xr, B=g_wa, epilogue scatters tf32-rounded q/k/v.
// MODE 1: A=g_y,  B=g_wp, epilogue writes fp32 row-major to Cout.
// ---------------------------------------------------------------------------
constexpr int APAD = 20, BPAD = 136;
constexpr int ASZ = 128 * APAD, BSZ = 16 * BPAD;
constexpr int GSTG = ASZ + BSZ; // words per stage
constexpr int GEMM_SMEM = 3 * GSTG * 4;

template <int MODE>
__global__ __launch_bounds__(256) void gemm_tf32(
    const float* __restrict__ bias, float* __restrict__ Cout,
    int M, int N, int K)
{
    extern __shared__ float sm[];

    const float* __restrict__ A = (MODE == 0) ? g_xr : g_y;
    const float* __restrict__ Bm = (MODE == 0) ? g_wa : g_wp;

    const int tid = threadIdx.x;
    const int lane = tid & 31;
    const int wid = tid >> 5;
    const int g = lane >> 2;
    const int t4 = lane & 3;
    const int wm = (wid & 3) * 32;
    const int wn = (wid >> 2) * 64;
    const int m0 = blockIdx.y * 128;
    const int n0 = blockIdx.x * 128;

    const int nt = K >> 4;

    auto issue = [&](int stage, int k0) {
        float* sA = sm + stage * GSTG;
        float* sB = sA + ASZ;
#pragma unroll
        for (int h = 0; h < 2; h++) {
            int c = tid + h * 256;
            int m = c >> 2, kc = (c & 3) * 4;
            cp_async16(smem_u32(&sA[m * APAD + kc]),
                       &A[(size_t)(m0 + m) * K + k0 + kc]);
        }
#pragma unroll
        for (int h = 0; h < 2; h++) {
            int c = tid + h * 256;
            int kr = c >> 5, nc = (c & 31) * 4;
            cp_async16(smem_u32(&sB[kr * BPAD + nc]),
                       &Bm[(size_t)(k0 + kr) * N + n0 + nc]);
        }
        cp_commit();
    };

    float acc[2][8][4] = {};

    issue(0, 0);
    issue(1, 16);

    for (int i = 0; i < nt; i++) {
        // Outstanding groups before wait: {i, i+1} for i<=nt-2, only {i} at tail.
        if (i == nt - 1) cp_wait<0>(); else cp_wait<1>();
        __syncthreads();
        if (i + 2 < nt) issue((i + 2) % 3, (i + 2) * 16);

        const float* sA = sm + (i % 3) * GSTG;
        const float* sB = sA + ASZ;

#pragma unroll
        for (int kk = 0; kk < 16; kk += 8) {
            uint32_t af[2][4];
#pragma unroll
            for (int mi = 0; mi < 2; mi++) {
                const int mb = wm + mi * 16 + g;
                af[mi][0] = __float_as_uint(sA[(mb) * APAD + kk + t4]);
                af[mi][1] = __float_as_uint(sA[(mb + 8) * APAD + kk + t4]);
                af[mi][2] = __float_as_uint(sA[(mb) * APAD + kk + t4 + 4]);
                af[mi][3] = __float_as_uint(sA[(mb + 8) * APAD + kk + t4 + 4]);
            }
            uint32_t bf[8][2];
#pragma unroll
            for (int ni = 0; ni < 8; ni++) {
                const int nb = wn + ni * 8 + g;
                bf[ni][0] = __float_as_uint(sB[(kk + t4) * BPAD + nb]);
                bf[ni][1] = __float_as_uint(sB[(kk + t4 + 4) * BPAD + nb]);
            }
#pragma unroll
            for (int mi = 0; mi < 2; mi++)
#pragma unroll
                for (int ni = 0; ni < 8; ni++)
                    mma_tf32(acc[mi][ni][0], acc[mi][ni][1], acc[mi][ni][2], acc[mi][ni][3],
                             af[mi][0], af[mi][1], af[mi][2], af[mi][3],
                             bf[ni][0], bf[ni][1]);
        }
    }

    // Epilogue
#pragma unroll
    for (int mi = 0; mi < 2; mi++) {
#pragma unroll
        for (int ni = 0; ni < 8; ni++) {
            const int r0 = m0 + wm + mi * 16 + g;
            const int r1 = r0 + 8;
            const int c0 = n0 + wn + ni * 8 + 2 * t4;
            const float bia = bias[c0];
            const float bib = bias[c0 + 1];
            float v00 = acc[mi][ni][0] + bia;
            float v01 = acc[mi][ni][1] + bib;
            float v10 = acc[mi][ni][2] + bia;
            float v11 = acc[mi][ni][3] + bib;
            if (MODE == 0) {
#pragma unroll
                for (int e = 0; e < 4; e++) {
                    const int m = (e < 2) ? r0 : r1;
                    const int n = c0 + (e & 1);
                    float v = (e == 0) ? v00 : (e == 1) ? v01 : (e == 2) ? v10 : v11;
                    v = roundtf(v); // q,k,v stored tf32-exact
                    const int part = n >> 10;
                    const int cc = n & 1023;
                    const int h = cc >> 6;
                    const int d = cc & 63;
                    const int b = m >> 11;
                    const int t = m & 2047;
                    float* dst = (part == 0) ? g_q : (part == 1) ? g_k : g_v;
                    dst[(((size_t)(b * H_ + h) * T_) + t) * HD + d] = v;
                }
            } else {
                *(float2*)&Cout[(size_t)r0 * N + c0] = make_float2(v00, v01);
                *(float2*)&Cout[(size_t)r1 * N + c0] = make_float2(v10, v11);
            }
        }
    }
}

// ---------------------------------------------------------------------------
// Row squared norms of q and k (inputs already tf32-rounded)
// ---------------------------------------------------------------------------
__global__ void q2k2_kernel() {
    const int idx = blockIdx.x * blockDim.x + threadIdx.x;
    if (idx >= BH * T_) return;
    const float4* q = (const float4*)(g_q + (size_t)idx * HD);
    const float4* k = (const float4*)(g_k + (size_t)idx * HD);
    float sq = 0.0f, sk = 0.0f;
#pragma unroll
    for (int i = 0; i < HD / 4; i++) {
        float4 a = q[i];
        sq += a.x * a.x + a.y * a.y + a.z * a.z + a.w * a.w;
        float4 b = k[i];
        sk += b.x * b.x + b.y * b.y + b.z * b.z + b.w * b.w;
    }
    g_q2[idx] = sq;
    g_k2[idx] = sk;
}

// ---------------------------------------------------------------------------
// Streaming causal Gaussian attention, tf32 mma, 2-stage cp.async K/V.
// Block = 128-row q-tile x bh. 256 thr = 8 warps (4 in M x 2 in N),
// warp tile 32x32 (mi=2, ni=4). K/V tiles 64x64 double-buffered.
// Smem: Q 128x68, S 128x68, K 2x64x68, V 2x64x72 = 141312 B -> 1 CTA/SM.
// ---------------------------------------------------------------------------
constexpr int QPAD = 68, VPAD = 72;
constexpr int Q_OFF = 0;
constexpr int S_OFF = 128 * QPAD;
constexpr int K_OFF = 2 * 128 * QPAD;           // 2 stages of 64*QPAD
constexpr int V_OFF = K_OFF + 2 * 64 * QPAD;    // 2 stages of 64*VPAD
constexpr int ATTN_SMEM = (V_OFF + 2 * 64 * VPAD) * 4;

__global__ __launch_bounds__(256) void attn_tf32() {
    extern __shared__ float sm[];
    float* Qs = sm + Q_OFF;
    float* Ss = sm + S_OFF;

    const int bh = blockIdx.y;
    const int qt = (int)gridDim.x - 1 - (int)blockIdx.x; // longest blocks first
    const int q0 = qt * 128;
    const int tid = threadIdx.x;
    const int lane = tid & 31;
    const int wid = tid >> 5;
    const int g = lane >> 2;
    const int t4 = lane & 3;
    const int wm = (wid & 3) * 32;   // q rows (0,32,64,96)
    const int wn = (wid >> 2) * 32;  // k cols / d cols (0,32)

    const float* __restrict__ qp = g_q + (size_t)bh * T_ * HD;
    const float* __restrict__ kp = g_k + (size_t)bh * T_ * HD;
    const float* __restrict__ vp = g_v + (size_t)bh * T_ * HD;

    // K/V tile 64x64 = 1024 16B-chunks each -> 4 per thread each.
    auto issueKV = [&](int stage, int k0) {
        float* Ks = sm + K_OFF + stage * 64 * QPAD;
        float* Vs = sm + V_OFF + stage * 64 * VPAD;
#pragma unroll
        for (int h = 0; h < 4; h++) {
            int c = tid + h * 256;
            int row = c >> 4, d4 = (c & 15) * 4;
            cp_async16(smem_u32(&Ks[row * QPAD + d4]), &kp[(size_t)(k0 + row) * HD + d4]);
            cp_async16(smem_u32(&Vs[row * VPAD + d4]), &vp[(size_t)(k0 + row) * HD + d4]);
        }
        cp_commit();
    };

    // Prologue: Q tile (128x64 = 2048 chunks, 8/thread) + first K/V stage.
    {
#pragma unroll
        for (int h = 0; h < 8; h++) {
            int c = tid + h * 256;
            int row = c >> 4, d4 = (c & 15) * 4;
            cp_async16(smem_u32(&Qs[row * QPAD + d4]), &qp[(size_t)(q0 + row) * HD + d4]);
        }
        issueKV(0, 0);
    }

    // q2 in registers (rows g, g+8 per mi)
    float q2v[4];
#pragma unroll
    for (int mi = 0; mi < 2; mi++) {
        q2v[mi * 2 + 0] = g_q2[bh * T_ + q0 + wm + mi * 16 + g];
        q2v[mi * 2 + 1] = g_q2[bh * T_ + q0 + wm + mi * 16 + g + 8];
    }

    float yacc[2][4][4] = {};

    const int ntile = 2 * qt + 2; // k-tiles of 64 covering [0, q0+128)

    for (int jt = 0; jt < ntile; jt++) {
        const int st = jt & 1;
        const int k0 = jt * 64;
        cp_wait<0>();     // full drain: stage st ready
        __syncthreads();  // prev SV reads of Ss/KV done across block
        if (jt + 1 < ntile) issueKV(st ^ 1, (jt + 1) * 64);

        // Warp fully above causal boundary for this k-tile? (rows all < k0)
        const bool full_mask = (k0 > q0 + wm + 31);

        const float* Ks = sm + K_OFF + st * 64 * QPAD;
        const float* Vs = sm + V_OFF + st * 64 * VPAD;

        if (!full_mask) {
            // k2 for this tile's 32 cols handled by this warp
            float2 k2c[4];
#pragma unroll
            for (int ni = 0; ni < 4; ni++)
                k2c[ni] = *(const float2*)&g_k2[bh * T_ + k0 + wn + ni * 8 + 2 * t4];

            // S = Q . K^T  (warp 32x32)
            float sacc[2][4][4] = {};
#pragma unroll
            for (int kk = 0; kk < 64; kk += 8) {
                uint32_t af[2][4];
#pragma unroll
                for (int mi = 0; mi < 2; mi++) {
                    const int mb = wm + mi * 16 + g;
                    af[mi][0] = __float_as_uint(Qs[(mb) * QPAD + kk + t4]);
                    af[mi][1] = __float_as_uint(Qs[(mb + 8) * QPAD + kk + t4]);
                    af[mi][2] = __float_as_uint(Qs[(mb) * QPAD + kk + t4 + 4]);
                    af[mi][3] = __float_as_uint(Qs[(mb + 8) * QPAD + kk + t4 + 4]);
                }
#pragma unroll
                for (int ni = 0; ni < 4; ni++) {
                    const int nb = wn + ni * 8 + g;
                    uint32_t b0 = __float_as_uint(Ks[(nb) * QPAD + kk + t4]);
                    uint32_t b1 = __float_as_uint(Ks[(nb) * QPAD + kk + t4 + 4]);
#pragma unroll
                    for (int mi = 0; mi < 2; mi++)
                        mma_tf32(sacc[mi][ni][0], sacc[mi][ni][1], sacc[mi][ni][2], sacc[mi][ni][3],
                                 af[mi][0], af[mi][1], af[mi][2], af[mi][3], b0, b1);
                }
            }

            // exp + causal mask (global index compare), store S tf32-rounded
#pragma unroll
            for (int mi = 0; mi < 2; mi++) {
#pragma unroll
                for (int ni = 0; ni < 4; ni++) {
                    const int r0l = wm + mi * 16 + g;
                    const int r1l = r0l + 8;
                    const int tq0 = q0 + r0l;
                    const int tq1 = q0 + r1l;
                    const int c0l = wn + ni * 8 + 2 * t4;
                    const int tk0 = k0 + c0l;
                    const int tk1 = tk0 + 1;
                    const float k2a = k2c[ni].x;
                    const float k2b = k2c[ni].y;
                    const float q2a = q2v[mi * 2 + 0];
                    const float q2b = q2v[mi * 2 + 1];
                    float e00 = __expf((q2a + k2a - 2.0f * sacc[mi][ni][0]) * SCALE);
                    float e01 = __expf((q2a + k2b - 2.0f * sacc[mi][ni][1]) * SCALE);
                    float e10 = __expf((q2b + k2a - 2.0f * sacc[mi][ni][2]) * SCALE);
                    float e11 = __expf((q2b + k2b - 2.0f * sacc[mi][ni][3]) * SCALE);
                    if (tk0 > tq0) e00 = 0.0f;
                    if (tk1 > tq0) e01 = 0.0f;
                    if (tk0 > tq1) e10 = 0.0f;
                    if (tk1 > tq1) e11 = 0.0f;
                    *(float2*)&Ss[r0l * QPAD + c0l] = make_float2(roundtf(e00), roundtf(e01));
                    *(float2*)&Ss[r1l * QPAD + c0l] = make_float2(roundtf(e10), roundtf(e11));
                }
            }
        }
        __syncthreads();  // S complete

        if (!full_mask) {
            // Y += S @ V  (warp 32 rows x 32 d-cols)
#pragma unroll
            for (int kk = 0; kk < 64; kk += 8) {
                uint32_t af[2][4];
#pragma unroll
                for (int mi = 0; mi < 2; mi++) {
                    const int mb = wm + mi * 16 + g;
                    af[mi][0] = __float_as_uint(Ss[(mb) * QPAD + kk + t4]);
                    af[mi][1] = __float_as_uint(Ss[(mb + 8) * QPAD + kk + t4]);
                    af[mi][2] = __float_as_uint(Ss[(mb) * QPAD + kk + t4 + 4]);
                    af[mi][3] = __float_as_uint(Ss[(mb + 8) * QPAD + kk + t4 + 4]);
                }
#pragma unroll
                for (int ni = 0; ni < 4; ni++) {
                    const int nb = wn + ni * 8 + g;
                    uint32_t b0 = __float_as_uint(Vs[(kk + t4) * VPAD + nb]);
                    uint32_t b1 = __float_as_uint(Vs[(kk + t4 + 4) * VPAD + nb]);
#pragma unroll
                    for (int mi = 0; mi < 2; mi++)
                        mma_tf32(yacc[mi][ni][0], yacc[mi][ni][1], yacc[mi][ni][2], yacc[mi][ni][3],
                                 af[mi][0], af[mi][1], af[mi][2], af[mi][3], b0, b1);
                }
            }
        }
    }

    // Write Y (tf32-rounded, consumed by proj mma) to (B,T,C)
    const int b = bh >> 4;
    const int h = bh & 15;
#pragma unroll
    for (int mi = 0; mi < 2; mi++) {
#pragma unroll
        for (int ni = 0; ni < 4; ni++) {
            const int t0 = q0 + wm + mi * 16 + g;
            const int t1 = t0 + 8;
            const int d = wn + ni * 8 + 2 * t4;
            *(float2*)&g_y[((size_t)(b * T_ + t0)) * C_ + h * HD + d] =
                make_float2(roundtf(yacc[mi][ni][0]), roundtf(yacc[mi][ni][1]));
            *(float2*)&g_y[((size_t)(b * T_ + t1)) * C_ + h * HD + d] =
                make_float2(roundtf(yacc[mi][ni][2]), roundtf(yacc[mi][ni][3]));
        }
    }
}

// ---------------------------------------------------------------------------
extern "C" void kernel_launch(void* const* d_in, const int* in_sizes, int n_in,
                              void* d_out, int out_size) {
    (void)in_sizes; (void)n_in; (void)out_size;
    const float* x      = (const float*)d_in[0];
    const float* W_attn = (const float*)d_in[1];
    const float* b_attn = (const float*)d_in[2];
    const float* W_proj = (const float*)d_in[3];
    const float* b_proj = (const float*)d_in[4];
    float* out = (float*)d_out;

    cudaFuncSetAttribute(gemm_tf32<0>, cudaFuncAttributeMaxDynamicSharedMemorySize, GEMM_SMEM);
    cudaFuncSetAttribute(gemm_tf32<1>, cudaFuncAttributeMaxDynamicSharedMemorySize, GEMM_SMEM);
    cudaFuncSetAttribute(attn_tf32, cudaFuncAttributeMaxDynamicSharedMemorySize, ATTN_SMEM);

    const size_t total4 = X4 + WA4 + WP4;
    prep_round<<<(unsigned)((total4 + 255) / 256), 256>>>(x, W_attn, W_proj);

    dim3 g1(N_QKV / 128, M_ROWS / 128);
    gemm_tf32<0><<<g1, 256, GEMM_SMEM>>>(b_attn, nullptr, M_ROWS, N_QKV, C_);

    q2k2_kernel<<<(BH * T_ + 255) / 256, 256>>>();

    attn_tf32<<<dim3(T_ / 128, BH), 256, ATTN_SMEM>>>();

    dim3 g2(C_ / 128, M_ROWS / 128);
    gemm_tf32<1><<<g2, 256, GEMM_SMEM>>>(b_proj, out, M_ROWS, C_, C_);
}

// round 7
// speedup vs baseline: 3.9936x; 1.1566x over previous
#include <cuda_runtime.h>
#include <cuda_fp16.h>
#include <cstdint>

// Problem constants
constexpr int B_ = 4;
constexpr int T_ = 2048;
constexpr int C_ = 1024;
constexpr int H_ = 16;
constexpr int HD = 64;
constexpr int BH = B_ * H_;     // 64
constexpr int M_ROWS = B_ * T_; // 8192
constexpr int N_QKV = 3 * C_;   // 3072

constexpr float SCALE = -1.0f / 16.0f; // -1/(2*sqrt(64))

// Device scratch (no cudaMalloc allowed)
__device__ __half g_qh[BH * T_ * HD];          // q, fp16, [bh][t][d]
__device__ __half g_kh[BH * T_ * HD];          // k, fp16, [bh][t][d]
__device__ __half g_vt[BH * HD * T_];          // v, fp16, TRANSPOSED [bh][d][t]
__device__ float g_y[M_ROWS * C_];
__device__ float g_q2[BH * T_];
__device__ float g_k2[BH * T_];
__device__ float g_xr[M_ROWS * C_];   // tf32-rounded x
__device__ float g_wa[C_ * N_QKV];    // tf32-rounded W_attn
__device__ float g_wp[C_ * C_];       // tf32-rounded W_proj

__device__ __forceinline__ uint32_t f2tf32(float x) {
    uint32_t r;
    asm("cvt.rna.tf32.f32 %0, %1;" : "=r"(r) : "f"(x));
    return r;
}
__device__ __forceinline__ float roundtf(float x) {
    return __uint_as_float(f2tf32(x));
}

__device__ __forceinline__ void mma_tf32(float& c0, float& c1, float& c2, float& c3,
                                         uint32_t a0, uint32_t a1, uint32_t a2, uint32_t a3,
                                         uint32_t b0, uint32_t b1) {
    asm volatile(
        "mma.sync.aligned.m16n8k8.row.col.f32.tf32.tf32.f32 "
        "{%0,%1,%2,%3}, {%4,%5,%6,%7}, {%8,%9}, {%0,%1,%2,%3};"
        : "+f"(c0), "+f"(c1), "+f"(c2), "+f"(c3)
        : "r"(a0), "r"(a1), "r"(a2), "r"(a3), "r"(b0), "r"(b1));
}

__device__ __forceinline__ void mma_f16(float& c0, float& c1, float& c2, float& c3,
                                        uint32_t a0, uint32_t a1, uint32_t a2, uint32_t a3,
                                        uint32_t b0, uint32_t b1) {
    asm volatile(
        "mma.sync.aligned.m16n8k16.row.col.f32.f16.f16.f32 "
        "{%0,%1,%2,%3}, {%4,%5,%6,%7}, {%8,%9}, {%0,%1,%2,%3};"
        : "+f"(c0), "+f"(c1), "+f"(c2), "+f"(c3)
        : "r"(a0), "r"(a1), "r"(a2), "r"(a3), "r"(b0), "r"(b1));
}

__device__ __forceinline__ void cp_async16(uint32_t dst, const void* src) {
    asm volatile("cp.async.cg.shared.global [%0], [%1], 16;" :: "r"(dst), "l"(src));
}
__device__ __forceinline__ void cp_commit() {
    asm volatile("cp.async.commit_group;");
}
template <int N>
__device__ __forceinline__ void cp_wait() {
    asm volatile("cp.async.wait_group %0;" :: "n"(N));
}
__device__ __forceinline__ uint32_t smem_u32(const void* p) {
    return (uint32_t)__cvta_generic_to_shared(p);
}

// ---------------------------------------------------------------------------
// Pre-round x, W_attn, W_proj to tf32-exact fp32 (so mma truncation is exact).
// ---------------------------------------------------------------------------
constexpr size_t X4 = (size_t)M_ROWS * C_ / 4;
constexpr size_t WA4 = (size_t)C_ * N_QKV / 4;
constexpr size_t WP4 = (size_t)C_ * C_ / 4;

__global__ void prep_round(const float* __restrict__ x,
                           const float* __restrict__ wa,
                           const float* __restrict__ wp) {
    size_t i = (size_t)blockIdx.x * blockDim.x + threadIdx.x;
    const float4* src;
    float4* dst;
    size_t off;
    if (i < X4) { src = (const float4*)x; dst = (float4*)g_xr; off = i; }
    else if (i < X4 + WA4) { src = (const float4*)wa; dst = (float4*)g_wa; off = i - X4; }
    else if (i < X4 + WA4 + WP4) { src = (const float4*)wp; dst = (float4*)g_wp; off = i - X4 - WA4; }
    else return;
    float4 v = src[off];
    v.x = roundtf(v.x); v.y = roundtf(v.y); v.z = roundtf(v.z); v.w = roundtf(v.w);
    dst[off] = v;
}

// ---------------------------------------------------------------------------
// Dense tf32 GEMM, 128x128x16 tile, 3-stage cp.async pipeline, 256 threads.
// MODE 0: A=g_xr, B=g_wa, epilogue scatters fp16 q/k (natural) and v (transposed).
// MODE 1: A=g_y,  B=g_wp, epilogue writes fp32 row-major to Cout.
// ---------------------------------------------------------------------------
constexpr int APAD = 20, BPAD = 136;
constexpr int ASZ = 128 * APAD, BSZ = 16 * BPAD;
constexpr int GSTG = ASZ + BSZ; // words per stage
constexpr int GEMM_SMEM = 3 * GSTG * 4;

template <int MODE>
__global__ __launch_bounds__(256) void gemm_tf32(
    const float* __restrict__ bias, float* __restrict__ Cout,
    int M, int N, int K)
{
    extern __shared__ float sm[];

    const float* __restrict__ A = (MODE == 0) ? g_xr : g_y;
    const float* __restrict__ Bm = (MODE == 0) ? g_wa : g_wp;

    const int tid = threadIdx.x;
    const int lane = tid & 31;
    const int wid = tid >> 5;
    const int g = lane >> 2;
    const int t4 = lane & 3;
    const int wm = (wid & 3) * 32;
    const int wn = (wid >> 2) * 64;
    const int m0 = blockIdx.y * 128;
    const int n0 = blockIdx.x * 128;

    const int nt = K >> 4;

    auto issue = [&](int stage, int k0) {
        float* sA = sm + stage * GSTG;
        float* sB = sA + ASZ;
#pragma unroll
        for (int h = 0; h < 2; h++) {
            int c = tid + h * 256;
            int m = c >> 2, kc = (c & 3) * 4;
            cp_async16(smem_u32(&sA[m * APAD + kc]),
                       &A[(size_t)(m0 + m) * K + k0 + kc]);
        }
#pragma unroll
        for (int h = 0; h < 2; h++) {
            int c = tid + h * 256;
            int kr = c >> 5, nc = (c & 31) * 4;
            cp_async16(smem_u32(&sB[kr * BPAD + nc]),
                       &Bm[(size_t)(k0 + kr) * N + n0 + nc]);
        }
        cp_commit();
    };

    float acc[2][8][4] = {};

    issue(0, 0);
    issue(1, 16);

    for (int i = 0; i < nt; i++) {
        // Outstanding groups before wait: {i, i+1} for i<=nt-2, only {i} at tail.
        if (i == nt - 1) cp_wait<0>(); else cp_wait<1>();
        __syncthreads();
        if (i + 2 < nt) issue((i + 2) % 3, (i + 2) * 16);

        const float* sA = sm + (i % 3) * GSTG;
        const float* sB = sA + ASZ;

#pragma unroll
        for (int kk = 0; kk < 16; kk += 8) {
            uint32_t af[2][4];
#pragma unroll
            for (int mi = 0; mi < 2; mi++) {
                const int mb = wm + mi * 16 + g;
                af[mi][0] = __float_as_uint(sA[(mb) * APAD + kk + t4]);
                af[mi][1] = __float_as_uint(sA[(mb + 8) * APAD + kk + t4]);
                af[mi][2] = __float_as_uint(sA[(mb) * APAD + kk + t4 + 4]);
                af[mi][3] = __float_as_uint(sA[(mb + 8) * APAD + kk + t4 + 4]);
            }
            uint32_t bf[8][2];
#pragma unroll
            for (int ni = 0; ni < 8; ni++) {
                const int nb = wn + ni * 8 + g;
                bf[ni][0] = __float_as_uint(sB[(kk + t4) * BPAD + nb]);
                bf[ni][1] = __float_as_uint(sB[(kk + t4 + 4) * BPAD + nb]);
            }
#pragma unroll
            for (int mi = 0; mi < 2; mi++)
#pragma unroll
                for (int ni = 0; ni < 8; ni++)
                    mma_tf32(acc[mi][ni][0], acc[mi][ni][1], acc[mi][ni][2], acc[mi][ni][3],
                             af[mi][0], af[mi][1], af[mi][2], af[mi][3],
                             bf[ni][0], bf[ni][1]);
        }
    }

    // Epilogue
#pragma unroll
    for (int mi = 0; mi < 2; mi++) {
#pragma unroll
        for (int ni = 0; ni < 8; ni++) {
            const int r0 = m0 + wm + mi * 16 + g;
            const int r1 = r0 + 8;
            const int c0 = n0 + wn + ni * 8 + 2 * t4;
            const float bia = bias[c0];
            const float bib = bias[c0 + 1];
            float v00 = acc[mi][ni][0] + bia;
            float v01 = acc[mi][ni][1] + bib;
            float v10 = acc[mi][ni][2] + bia;
            float v11 = acc[mi][ni][3] + bib;
            if (MODE == 0) {
#pragma unroll
                for (int e = 0; e < 4; e++) {
                    const int m = (e < 2) ? r0 : r1;
                    const int n = c0 + (e & 1);
                    const float v = (e == 0) ? v00 : (e == 1) ? v01 : (e == 2) ? v10 : v11;
                    const int part = n >> 10;
                    const int cc = n & 1023;
                    const int h = cc >> 6;
                    const int d = cc & 63;
                    const int b = m >> 11;
                    const int t = m & 2047;
                    const int bh = b * H_ + h;
                    const __half hv = __float2half_rn(v);
                    if (part == 0)
                        g_qh[((size_t)bh * T_ + t) * HD + d] = hv;
                    else if (part == 1)
                        g_kh[((size_t)bh * T_ + t) * HD + d] = hv;
                    else
                        g_vt[((size_t)bh * HD + d) * T_ + t] = hv; // transposed
                }
            } else {
                *(float2*)&Cout[(size_t)r0 * N + c0] = make_float2(v00, v01);
                *(float2*)&Cout[(size_t)r1 * N + c0] = make_float2(v10, v11);
            }
        }
    }
}

// ---------------------------------------------------------------------------
// Row squared norms of q and k from the fp16-rounded values (consistency with mma)
// ---------------------------------------------------------------------------
__global__ void q2k2_kernel() {
    const int idx = blockIdx.x * blockDim.x + threadIdx.x;
    if (idx >= BH * T_) return;
    const half2* q = (const half2*)(g_qh + (size_t)idx * HD);
    const half2* k = (const half2*)(g_kh + (size_t)idx * HD);
    float sq = 0.0f, sk = 0.0f;
#pragma unroll
    for (int i = 0; i < HD / 2; i++) {
        float2 a = __half22float2(q[i]);
        sq += a.x * a.x + a.y * a.y;
        float2 b = __half22float2(k[i]);
        sk += b.x * b.x + b.y * b.y;
    }
    g_q2[idx] = sq;
    g_k2[idx] = sk;
}

// ---------------------------------------------------------------------------
// Streaming causal Gaussian attention, fp16 mma (m16n8k16), 2-stage cp.async.
// Block = 128-row q-tile x bh. 256 thr = 8 warps (4 M x 2 N), warp tile 32x32.
// All tiles fp16, row pitch 72 halves (144 B -> banks 4g+t4, conflict-free).
// Smem: Q 128x72 + S 128x72 + K 2x64x72 + V^T 2x64x72 = 36864 halves = 72 KB
// -> 2 CTAs/SM (16 warps/SM).
// ---------------------------------------------------------------------------
constexpr int QP = 72; // halves per row
constexpr int Q_OFF = 0;
constexpr int S_OFF = 128 * QP;                 // 9216
constexpr int K_OFF = S_OFF + 128 * QP;         // 18432 (2 stages of 64*QP)
constexpr int V_OFF = K_OFF + 2 * 64 * QP;      // 27648 (2 stages of 64*QP)
constexpr int ATTN_SMEM = (V_OFF + 2 * 64 * QP) * 2; // bytes

__global__ __launch_bounds__(256) void attn_f16() {
    extern __shared__ __half smh[];
    __half* Qs = smh + Q_OFF;
    __half* Ss = smh + S_OFF;

    const int bh = blockIdx.y;
    const int qt = (int)gridDim.x - 1 - (int)blockIdx.x; // longest blocks first
    const int q0 = qt * 128;
    const int tid = threadIdx.x;
    const int lane = tid & 31;
    const int wid = tid >> 5;
    const int g = lane >> 2;
    const int t4 = lane & 3;
    const int wm = (wid & 3) * 32;   // q rows (0,32,64,96)
    const int wn = (wid >> 2) * 32;  // k cols / d cols (0,32)

    const __half* __restrict__ qp = g_qh + (size_t)bh * T_ * HD;
    const __half* __restrict__ kp = g_kh + (size_t)bh * T_ * HD;
    const __half* __restrict__ vtp = g_vt + (size_t)bh * HD * T_;

    // K tile 64x64 halves (8KB) = 512 16B-chunks; V^T tile same. 2 each/thread.
    auto issueKV = [&](int stage, int k0) {
        __half* Ks = smh + K_OFF + stage * 64 * QP;
        __half* Vs = smh + V_OFF + stage * 64 * QP;
#pragma unroll
        for (int h2 = 0; h2 < 2; h2++) {
            int c = tid + h2 * 256;
            int row = c >> 3, cc = (c & 7) * 8;
            cp_async16(smem_u32(&Ks[row * QP + cc]), &kp[(size_t)(k0 + row) * HD + cc]);
            // V^T: row = d (0..63), cols = tokens k0+cc..
            cp_async16(smem_u32(&Vs[row * QP + cc]), &vtp[(size_t)row * T_ + k0 + cc]);
        }
        cp_commit();
    };

    // Prologue: Q tile (128x64 halves = 1024 chunks, 4/thread) + first K/V stage.
    {
#pragma unroll
        for (int h2 = 0; h2 < 4; h2++) {
            int c = tid + h2 * 256;
            int row = c >> 3, cc = (c & 7) * 8;
            cp_async16(smem_u32(&Qs[row * QP + cc]), &qp[(size_t)(q0 + row) * HD + cc]);
        }
        issueKV(0, 0);
    }

    // q2 in registers (rows g, g+8 per mi)
    float q2v[4];
#pragma unroll
    for (int mi = 0; mi < 2; mi++) {
        q2v[mi * 2 + 0] = g_q2[bh * T_ + q0 + wm + mi * 16 + g];
        q2v[mi * 2 + 1] = g_q2[bh * T_ + q0 + wm + mi * 16 + g + 8];
    }

    float yacc[2][4][4] = {};

    const int ntile = 2 * qt + 2; // k-tiles of 64 covering [0, q0+128)

    for (int jt = 0; jt < ntile; jt++) {
        const int st = jt & 1;
        const int k0 = jt * 64;
        cp_wait<0>();     // stage st ready
        __syncthreads();  // prev SV reads of Ss/KV done across block
        if (jt + 1 < ntile) issueKV(st ^ 1, (jt + 1) * 64);

        // Warp fully above causal boundary for this k-tile?
        const bool full_mask = (k0 > q0 + wm + 31);

        const __half* Ks = smh + K_OFF + st * 64 * QP;
        const __half* Vs = smh + V_OFF + st * 64 * QP;

        if (!full_mask) {
            float2 k2c[4];
#pragma unroll
            for (int ni = 0; ni < 4; ni++)
                k2c[ni] = *(const float2*)&g_k2[bh * T_ + k0 + wn + ni * 8 + 2 * t4];

            // S = Q . K^T   (m16n8k16, k = d, 4 steps)
            float sacc[2][4][4] = {};
#pragma unroll
            for (int kk = 0; kk < 64; kk += 16) {
                uint32_t af[2][4];
#pragma unroll
                for (int mi = 0; mi < 2; mi++) {
                    const int mb = wm + mi * 16 + g;
                    af[mi][0] = *(const uint32_t*)&Qs[(mb) * QP + kk + 2 * t4];
                    af[mi][1] = *(const uint32_t*)&Qs[(mb + 8) * QP + kk + 2 * t4];
                    af[mi][2] = *(const uint32_t*)&Qs[(mb) * QP + kk + 8 + 2 * t4];
                    af[mi][3] = *(const uint32_t*)&Qs[(mb + 8) * QP + kk + 8 + 2 * t4];
                }
#pragma unroll
                for (int ni = 0; ni < 4; ni++) {
                    const int nb = wn + ni * 8 + g; // token col
                    uint32_t b0 = *(const uint32_t*)&Ks[(nb) * QP + kk + 2 * t4];
                    uint32_t b1 = *(const uint32_t*)&Ks[(nb) * QP + kk + 8 + 2 * t4];
#pragma unroll
                    for (int mi = 0; mi < 2; mi++)
                        mma_f16(sacc[mi][ni][0], sacc[mi][ni][1], sacc[mi][ni][2], sacc[mi][ni][3],
                                af[mi][0], af[mi][1], af[mi][2], af[mi][3], b0, b1);
                }
            }

            // exp + causal mask, store S as half2
#pragma unroll
            for (int mi = 0; mi < 2; mi++) {
#pragma unroll
                for (int ni = 0; ni < 4; ni++) {
                    const int r0l = wm + mi * 16 + g;
                    const int r1l = r0l + 8;
                    const int tq0 = q0 + r0l;
                    const int tq1 = q0 + r1l;
                    const int c0l = wn + ni * 8 + 2 * t4;
                    const int tk0 = k0 + c0l;
                    const int tk1 = tk0 + 1;
                    const float k2a = k2c[ni].x;
                    const float k2b = k2c[ni].y;
                    const float q2a = q2v[mi * 2 + 0];
                    const float q2b = q2v[mi * 2 + 1];
                    float e00 = __expf((q2a + k2a - 2.0f * sacc[mi][ni][0]) * SCALE);
                    float e01 = __expf((q2a + k2b - 2.0f * sacc[mi][ni][1]) * SCALE);
                    float e10 = __expf((q2b + k2a - 2.0f * sacc[mi][ni][2]) * SCALE);
                    float e11 = __expf((q2b + k2b - 2.0f * sacc[mi][ni][3]) * SCALE);
                    if (tk0 > tq0) e00 = 0.0f;
                    if (tk1 > tq0) e01 = 0.0f;
                    if (tk0 > tq1) e10 = 0.0f;
                    if (tk1 > tq1) e11 = 0.0f;
                    *(half2*)&Ss[r0l * QP + c0l] = __floats2half2_rn(e00, e01);
                    *(half2*)&Ss[r1l * QP + c0l] = __floats2half2_rn(e10, e11);
                }
            }
        }
        __syncthreads();  // S complete

        if (!full_mask) {
            // Y += S @ V   (m16n8k16, k = token, A = S, B = V^T)
#pragma unroll
            for (int kk = 0; kk < 64; kk += 16) {
                uint32_t af[2][4];
#pragma unroll
                for (int mi = 0; mi < 2; mi++) {
                    const int mb = wm + mi * 16 + g;
                    af[mi][0] = *(const uint32_t*)&Ss[(mb) * QP + kk + 2 * t4];
                    af[mi][1] = *(const uint32_t*)&Ss[(mb + 8) * QP + kk + 2 * t4];
                    af[mi][2] = *(const uint32_t*)&Ss[(mb) * QP + kk + 8 + 2 * t4];
                    af[mi][3] = *(const uint32_t*)&Ss[(mb + 8) * QP + kk + 8 + 2 * t4];
                }
#pragma unroll
                for (int ni = 0; ni < 4; ni++) {
                    const int nb = wn + ni * 8 + g; // d col
                    uint32_t b0 = *(const uint32_t*)&Vs[(nb) * QP + kk + 2 * t4];
                    uint32_t b1 = *(const uint32_t*)&Vs[(nb) * QP + kk + 8 + 2 * t4];
#pragma unroll
                    for (int mi = 0; mi < 2; mi++)
                        mma_f16(yacc[mi][ni][0], yacc[mi][ni][1], yacc[mi][ni][2], yacc[mi][ni][3],
                                af[mi][0], af[mi][1], af[mi][2], af[mi][3], b0, b1);
                }
            }
        }
    }

    // Write Y (tf32-rounded, consumed by proj mma) to (B,T,C)
    const int b = bh >> 4;
    const int h = bh & 15;
#pragma unroll
    for (int mi = 0; mi < 2; mi++) {
#pragma unroll
        for (int ni = 0; ni < 4; ni++) {
            const int t0 = q0 + wm + mi * 16 + g;
            const int t1 = t0 + 8;
            const int d = wn + ni * 8 + 2 * t4;
            *(float2*)&g_y[((size_t)(b * T_ + t0)) * C_ + h * HD + d] =
                make_float2(roundtf(yacc[mi][ni][0]), roundtf(yacc[mi][ni][1]));
            *(float2*)&g_y[((size_t)(b * T_ + t1)) * C_ + h * HD + d] =
                make_float2(roundtf(yacc[mi][ni][2]), roundtf(yacc[mi][ni][3]));
        }
    }
}

// ---------------------------------------------------------------------------
extern "C" void kernel_launch(void* const* d_in, const int* in_sizes, int n_in,
                              void* d_out, int out_size) {
    (void)in_sizes; (void)n_in; (void)out_size;
    const float* x      = (const float*)d_in[0];
    const float* W_attn = (const float*)d_in[1];
    const float* b_attn = (const float*)d_in[2];
    const float* W_proj = (const float*)d_in[3];
    const float* b_proj = (const float*)d_in[4];
    float* out = (float*)d_out;

    cudaFuncSetAttribute(gemm_tf32<0>, cudaFuncAttributeMaxDynamicSharedMemorySize, GEMM_SMEM);
    cudaFuncSetAttribute(gemm_tf32<1>, cudaFuncAttributeMaxDynamicSharedMemorySize, GEMM_SMEM);
    cudaFuncSetAttribute(attn_f16, cudaFuncAttributeMaxDynamicSharedMemorySize, ATTN_SMEM);

    const size_t total4 = X4 + WA4 + WP4;
    prep_round<<<(unsigned)((total4 + 255) / 256), 256>>>(x, W_attn, W_proj);

    dim3 g1(N_QKV / 128, M_ROWS / 128);
    gemm_tf32<0><<<g1, 256, GEMM_SMEM>>>(b_attn, nullptr, M_ROWS, N_QKV, C_);

    q2k2_kernel<<<(BH * T_ + 255) / 256, 256>>>();

    attn_f16<<<dim3(T_ / 128, BH), 256, ATTN_SMEM>>>();

    dim3 g2(C_ / 128, M_ROWS / 128);
    gemm_tf32<1><<<g2, 256, GEMM_SMEM>>>(b_proj, out, M_ROWS, C_, C_);
}

// round 9
// speedup vs baseline: 5.4852x; 1.3735x over previous
#include <cuda_runtime.h>
#include <cuda_fp16.h>
#include <cstdint>

// Problem constants
constexpr int B_ = 4;
constexpr int T_ = 2048;
constexpr int C_ = 1024;
constexpr int H_ = 16;
constexpr int HD = 64;
constexpr int BH = B_ * H_;     // 64
constexpr int M_ROWS = B_ * T_; // 8192
constexpr int N_QKV = 3 * C_;   // 3072

constexpr float SCALE = -1.0f / 16.0f; // -1/(2*sqrt(64))

// Device scratch (no cudaMalloc allowed). NOTE: device globals must only be
// referenced from device code (host-passed device symbols are UB -> R8 crash).
__device__ __half g_qh[BH * T_ * HD];   // q fp16 [bh][t][d]
__device__ __half g_kh[BH * T_ * HD];   // k fp16 [bh][t][d]
__device__ __half g_vt[BH * HD * T_];   // v fp16 TRANSPOSED [bh][d][t]
__device__ __half g_yh[M_ROWS * C_];    // attention output, fp16 [m][c]
__device__ __half g_xh[M_ROWS * C_];    // x rounded to fp16 [m][k]
__device__ __half g_wat[N_QKV * C_];    // W_attn^T fp16 [n][k]
__device__ __half g_wpt[C_ * C_];       // W_proj^T fp16 [n][k]
__device__ float g_q2[BH * T_];
__device__ float g_k2[BH * T_];

__device__ __forceinline__ void mma_f16(float& c0, float& c1, float& c2, float& c3,
                                        uint32_t a0, uint32_t a1, uint32_t a2, uint32_t a3,
                                        uint32_t b0, uint32_t b1) {
    asm volatile(
        "mma.sync.aligned.m16n8k16.row.col.f32.f16.f16.f32 "
        "{%0,%1,%2,%3}, {%4,%5,%6,%7}, {%8,%9}, {%0,%1,%2,%3};"
        : "+f"(c0), "+f"(c1), "+f"(c2), "+f"(c3)
        : "r"(a0), "r"(a1), "r"(a2), "r"(a3), "r"(b0), "r"(b1));
}

__device__ __forceinline__ void cp_async16(uint32_t dst, const void* src) {
    asm volatile("cp.async.cg.shared.global [%0], [%1], 16;" :: "r"(dst), "l"(src));
}
__device__ __forceinline__ void cp_commit() {
    asm volatile("cp.async.commit_group;");
}
template <int N>
__device__ __forceinline__ void cp_wait() {
    asm volatile("cp.async.wait_group %0;" :: "n"(N));
}
__device__ __forceinline__ uint32_t smem_u32(const void* p) {
    return (uint32_t)__cvta_generic_to_shared(p);
}

// ---------------------------------------------------------------------------
// Prep: round x to fp16; transpose W matrices to N-major fp16.
// ---------------------------------------------------------------------------
__global__ void round_x(const float* __restrict__ x) {
    size_t i = (size_t)blockIdx.x * blockDim.x + threadIdx.x; // float4 index
    if (i >= (size_t)M_ROWS * C_ / 4) return;
    float4 v = ((const float4*)x)[i];
    half2 lo = __floats2half2_rn(v.x, v.y);
    half2 hi = __floats2half2_rn(v.z, v.w);
    ((half2*)g_xh)[i * 2 + 0] = lo;
    ((half2*)g_xh)[i * 2 + 1] = hi;
}

// in: [K][N] fp32 row-major -> out: [N][K] fp16 row-major.
// WSEL selects the device-global destination INSIDE device code.
template <int WSEL>
__global__ void transpose_half(const float* __restrict__ in, int K, int N) {
    __half* __restrict__ out = (WSEL == 0) ? g_wat : g_wpt;
    __shared__ float tile[32][33];
    const int n0 = blockIdx.x * 32;
    const int k0 = blockIdx.y * 32;
    const int tx = threadIdx.x; // 0..31
    const int ty = threadIdx.y; // 0..7
#pragma unroll
    for (int j = 0; j < 4; j++)
        tile[ty + j * 8][tx] = in[(size_t)(k0 + ty + j * 8) * N + n0 + tx];
    __syncthreads();
#pragma unroll
    for (int j = 0; j < 4; j++)
        out[(size_t)(n0 + ty + j * 8) * K + k0 + tx] =
            __float2half_rn(tile[tx][ty + j * 8]);
}

// ---------------------------------------------------------------------------
// Dense fp16 GEMM: C = A(MxK) * B^T stored [N][K] + bias, fp32 accum.
// 128x128x32 tile, 3-stage cp.async, 256 threads = 8 warps (4M x 2N),
// warp 32x64 (mi=2, ni=8). Row pitch 40 halves.
// MODE 0: A=g_xh, B=g_wat, epilogue scatters fp16 q/k (natural) + v transposed.
// MODE 1: A=g_yh, B=g_wpt, epilogue writes fp32 to Cout.
// ---------------------------------------------------------------------------
constexpr int BKH = 32;  // k per tile (halves)
constexpr int HP = 40;   // halves per row in smem
constexpr int HASZ = 128 * HP;           // halves
constexpr int HSTG = 2 * HASZ;           // A + B per stage
constexpr int GEMM_SMEM = 3 * HSTG * 2;  // bytes (61440)

template <int MODE>
__global__ __launch_bounds__(256) void gemm_f16(
    const float* __restrict__ bias, float* __restrict__ Cout,
    int M, int N, int K)
{
    extern __shared__ __half smh[];

    const __half* __restrict__ A = (MODE == 0) ? g_xh : g_yh;
    const __half* __restrict__ Bt = (MODE == 0) ? g_wat : g_wpt;

    const int tid = threadIdx.x;
    const int lane = tid & 31;
    const int wid = tid >> 5;
    const int g = lane >> 2;
    const int t4 = lane & 3;
    const int wm = (wid & 3) * 32;
    const int wn = (wid >> 2) * 64;
    const int m0 = blockIdx.y * 128;
    const int n0 = blockIdx.x * 128;

    const int nt = K / BKH;

    auto issue = [&](int stage, int k0) {
        __half* sA = smh + stage * HSTG;
        __half* sB = sA + HASZ;
        // 128 rows x 32 halves = 512 16B-chunks each, 2/thread each
#pragma unroll
        for (int h = 0; h < 2; h++) {
            int c = tid + h * 256;
            int row = c >> 2, c8 = (c & 3) * 8;
            cp_async16(smem_u32(&sA[row * HP + c8]), &A[(size_t)(m0 + row) * K + k0 + c8]);
            cp_async16(smem_u32(&sB[row * HP + c8]), &Bt[(size_t)(n0 + row) * K + k0 + c8]);
        }
        cp_commit();
    };

    float acc[2][8][4] = {};

    issue(0, 0);
    issue(1, BKH);

    for (int i = 0; i < nt; i++) {
        // Outstanding groups before wait: {i, i+1} for i<=nt-2, only {i} at tail.
        if (i == nt - 1) cp_wait<0>(); else cp_wait<1>();
        __syncthreads();
        if (i + 2 < nt) issue((i + 2) % 3, (i + 2) * BKH);

        const __half* sA = smh + (i % 3) * HSTG;
        const __half* sB = sA + HASZ;

#pragma unroll
        for (int kk = 0; kk < BKH; kk += 16) {
            uint32_t af[2][4];
#pragma unroll
            for (int mi = 0; mi < 2; mi++) {
                const int mb = wm + mi * 16 + g;
                af[mi][0] = *(const uint32_t*)&sA[(mb) * HP + kk + 2 * t4];
                af[mi][1] = *(const uint32_t*)&sA[(mb + 8) * HP + kk + 2 * t4];
                af[mi][2] = *(const uint32_t*)&sA[(mb) * HP + kk + 8 + 2 * t4];
                af[mi][3] = *(const uint32_t*)&sA[(mb + 8) * HP + kk + 8 + 2 * t4];
            }
            uint32_t bf[8][2];
#pragma unroll
            for (int ni = 0; ni < 8; ni++) {
                const int nb = wn + ni * 8 + g;
                bf[ni][0] = *(const uint32_t*)&sB[(nb) * HP + kk + 2 * t4];
                bf[ni][1] = *(const uint32_t*)&sB[(nb) * HP + kk + 8 + 2 * t4];
            }
#pragma unroll
            for (int mi = 0; mi < 2; mi++)
#pragma unroll
                for (int ni = 0; ni < 8; ni++)
                    mma_f16(acc[mi][ni][0], acc[mi][ni][1], acc[mi][ni][2], acc[mi][ni][3],
                            af[mi][0], af[mi][1], af[mi][2], af[mi][3],
                            bf[ni][0], bf[ni][1]);
        }
    }

    // Epilogue
#pragma unroll
    for (int mi = 0; mi < 2; mi++) {
#pragma unroll
        for (int ni = 0; ni < 8; ni++) {
            const int r0 = m0 + wm + mi * 16 + g;
            const int r1 = r0 + 8;
            const int c0 = n0 + wn + ni * 8 + 2 * t4;
            const float bia = bias[c0];
            const float bib = bias[c0 + 1];
            float v00 = acc[mi][ni][0] + bia;
            float v01 = acc[mi][ni][1] + bib;
            float v10 = acc[mi][ni][2] + bia;
            float v11 = acc[mi][ni][3] + bib;
            if (MODE == 0) {
#pragma unroll
                for (int e = 0; e < 4; e++) {
                    const int m = (e < 2) ? r0 : r1;
                    const int n = c0 + (e & 1);
                    const float v = (e == 0) ? v00 : (e == 1) ? v01 : (e == 2) ? v10 : v11;
                    const int part = n >> 10;
                    const int cc = n & 1023;
                    const int h = cc >> 6;
                    const int d = cc & 63;
                    const int b = m >> 11;
                    const int t = m & 2047;
                    const int bh = b * H_ + h;
                    const __half hv = __float2half_rn(v);
                    if (part == 0)
                        g_qh[((size_t)bh * T_ + t) * HD + d] = hv;
                    else if (part == 1)
                        g_kh[((size_t)bh * T_ + t) * HD + d] = hv;
                    else
                        g_vt[((size_t)bh * HD + d) * T_ + t] = hv; // transposed
                }
            } else {
                *(float2*)&Cout[(size_t)r0 * N + c0] = make_float2(v00, v01);
                *(float2*)&Cout[(size_t)r1 * N + c0] = make_float2(v10, v11);
            }
        }
    }
}

// ---------------------------------------------------------------------------
// Row squared norms of q and k from the fp16-rounded values
// ---------------------------------------------------------------------------
__global__ void q2k2_kernel() {
    const int idx = blockIdx.x * blockDim.x + threadIdx.x;
    if (idx >= BH * T_) return;
    const half2* q = (const half2*)(g_qh + (size_t)idx * HD);
    const half2* k = (const half2*)(g_kh + (size_t)idx * HD);
    float sq = 0.0f, sk = 0.0f;
#pragma unroll
    for (int i = 0; i < HD / 2; i++) {
        float2 a = __half22float2(q[i]);
        sq += a.x * a.x + a.y * a.y;
        float2 b = __half22float2(k[i]);
        sk += b.x * b.x + b.y * b.y;
    }
    g_q2[idx] = sq;
    g_k2[idx] = sk;
}

// ---------------------------------------------------------------------------
// Streaming causal Gaussian attention, fp16 mma (m16n8k16), 2-stage cp.async.
// Block = 128-row q-tile x bh. 256 thr = 8 warps (4 M x 2 N), warp tile 32x32.
// Smem: Q 128x72 + S 128x72 + K 2x64x72 + V^T 2x64x72 halves = 72 KB -> 2 CTAs/SM.
// ---------------------------------------------------------------------------
constexpr int QP = 72; // halves per row
constexpr int Q_OFF = 0;
constexpr int S_OFF = 128 * QP;
constexpr int K_OFF = S_OFF + 128 * QP;
constexpr int V_OFF = K_OFF + 2 * 64 * QP;
constexpr int ATTN_SMEM = (V_OFF + 2 * 64 * QP) * 2; // bytes

__global__ __launch_bounds__(256) void attn_f16() {
    extern __shared__ __half smh[];
    __half* Qs = smh + Q_OFF;
    __half* Ss = smh + S_OFF;

    const int bh = blockIdx.y;
    const int qt = (int)gridDim.x - 1 - (int)blockIdx.x; // longest blocks first
    const int q0 = qt * 128;
    const int tid = threadIdx.x;
    const int lane = tid & 31;
    const int wid = tid >> 5;
    const int g = lane >> 2;
    const int t4 = lane & 3;
    const int wm = (wid & 3) * 32;   // q rows
    const int wn = (wid >> 2) * 32;  // k cols / d cols

    const __half* __restrict__ qp = g_qh + (size_t)bh * T_ * HD;
    const __half* __restrict__ kp = g_kh + (size_t)bh * T_ * HD;
    const __half* __restrict__ vtp = g_vt + (size_t)bh * HD * T_;

    auto issueKV = [&](int stage, int k0) {
        __half* Ks = smh + K_OFF + stage * 64 * QP;
        __half* Vs = smh + V_OFF + stage * 64 * QP;
#pragma unroll
        for (int h2 = 0; h2 < 2; h2++) {
            int c = tid + h2 * 256;
            int row = c >> 3, cc = (c & 7) * 8;
            cp_async16(smem_u32(&Ks[row * QP + cc]), &kp[(size_t)(k0 + row) * HD + cc]);
            cp_async16(smem_u32(&Vs[row * QP + cc]), &vtp[(size_t)row * T_ + k0 + cc]);
        }
        cp_commit();
    };

    {
#pragma unroll
        for (int h2 = 0; h2 < 4; h2++) {
            int c = tid + h2 * 256;
            int row = c >> 3, cc = (c & 7) * 8;
            cp_async16(smem_u32(&Qs[row * QP + cc]), &qp[(size_t)(q0 + row) * HD + cc]);
        }
        issueKV(0, 0);
    }

    float q2v[4];
#pragma unroll
    for (int mi = 0; mi < 2; mi++) {
        q2v[mi * 2 + 0] = g_q2[bh * T_ + q0 + wm + mi * 16 + g];
        q2v[mi * 2 + 1] = g_q2[bh * T_ + q0 + wm + mi * 16 + g + 8];
    }

    float yacc[2][4][4] = {};

    const int ntile = 2 * qt + 2;

    for (int jt = 0; jt < ntile; jt++) {
        const int st = jt & 1;
        const int k0 = jt * 64;
        cp_wait<0>();
        __syncthreads();
        if (jt + 1 < ntile) issueKV(st ^ 1, (jt + 1) * 64);

        const bool full_mask = (k0 > q0 + wm + 31);

        const __half* Ks = smh + K_OFF + st * 64 * QP;
        const __half* Vs = smh + V_OFF + st * 64 * QP;

        if (!full_mask) {
            float2 k2c[4];
#pragma unroll
            for (int ni = 0; ni < 4; ni++)
                k2c[ni] = *(const float2*)&g_k2[bh * T_ + k0 + wn + ni * 8 + 2 * t4];

            float sacc[2][4][4] = {};
#pragma unroll
            for (int kk = 0; kk < 64; kk += 16) {
                uint32_t af[2][4];
#pragma unroll
                for (int mi = 0; mi < 2; mi++) {
                    const int mb = wm + mi * 16 + g;
                    af[mi][0] = *(const uint32_t*)&Qs[(mb) * QP + kk + 2 * t4];
                    af[mi][1] = *(const uint32_t*)&Qs[(mb + 8) * QP + kk + 2 * t4];
                    af[mi][2] = *(const uint32_t*)&Qs[(mb) * QP + kk + 8 + 2 * t4];
                    af[mi][3] = *(const uint32_t*)&Qs[(mb + 8) * QP + kk + 8 + 2 * t4];
                }
#pragma unroll
                for (int ni = 0; ni < 4; ni++) {
                    const int nb = wn + ni * 8 + g;
                    uint32_t b0 = *(const uint32_t*)&Ks[(nb) * QP + kk + 2 * t4];
                    uint32_t b1 = *(const uint32_t*)&Ks[(nb) * QP + kk + 8 + 2 * t4];
#pragma unroll
                    for (int mi = 0; mi < 2; mi++)
                        mma_f16(sacc[mi][ni][0], sacc[mi][ni][1], sacc[mi][ni][2], sacc[mi][ni][3],
                                af[mi][0], af[mi][1], af[mi][2], af[mi][3], b0, b1);
                }
            }

#pragma unroll
            for (int mi = 0; mi < 2; mi++) {
#pragma unroll
                for (int ni = 0; ni < 4; ni++) {
                    const int r0l = wm + mi * 16 + g;
                    const int r1l = r0l + 8;
                    const int tq0 = q0 + r0l;
                    const int tq1 = q0 + r1l;
                    const int c0l = wn + ni * 8 + 2 * t4;
                    const int tk0 = k0 + c0l;
                    const int tk1 = tk0 + 1;
                    const float k2a = k2c[ni].x;
                    const float k2b = k2c[ni].y;
                    const float q2a = q2v[mi * 2 + 0];
                    const float q2b = q2v[mi * 2 + 1];
                    float e00 = __expf((q2a + k2a - 2.0f * sacc[mi][ni][0]) * SCALE);
                    float e01 = __expf((q2a + k2b - 2.0f * sacc[mi][ni][1]) * SCALE);
                    float e10 = __expf((q2b + k2a - 2.0f * sacc[mi][ni][2]) * SCALE);
                    float e11 = __expf((q2b + k2b - 2.0f * sacc[mi][ni][3]) * SCALE);
                    if (tk0 > tq0) e00 = 0.0f;
                    if (tk1 > tq0) e01 = 0.0f;
                    if (tk0 > tq1) e10 = 0.0f;
                    if (tk1 > tq1) e11 = 0.0f;
                    *(half2*)&Ss[r0l * QP + c0l] = __floats2half2_rn(e00, e01);
                    *(half2*)&Ss[r1l * QP + c0l] = __floats2half2_rn(e10, e11);
                }
            }
        }
        __syncthreads();

        if (!full_mask) {
#pragma unroll
            for (int kk = 0; kk < 64; kk += 16) {
                uint32_t af[2][4];
#pragma unroll
                for (int mi = 0; mi < 2; mi++) {
                    const int mb = wm + mi * 16 + g;
                    af[mi][0] = *(const uint32_t*)&Ss[(mb) * QP + kk + 2 * t4];
                    af[mi][1] = *(const uint32_t*)&Ss[(mb + 8) * QP + kk + 2 * t4];
                    af[mi][2] = *(const uint32_t*)&Ss[(mb) * QP + kk + 8 + 2 * t4];
                    af[mi][3] = *(const uint32_t*)&Ss[(mb + 8) * QP + kk + 8 + 2 * t4];
                }
#pragma unroll
                for (int ni = 0; ni < 4; ni++) {
                    const int nb = wn + ni * 8 + g;
                    uint32_t b0 = *(const uint32_t*)&Vs[(nb) * QP + kk + 2 * t4];
                    uint32_t b1 = *(const uint32_t*)&Vs[(nb) * QP + kk + 8 + 2 * t4];
#pragma unroll
                    for (int mi = 0; mi < 2; mi++)
                        mma_f16(yacc[mi][ni][0], yacc[mi][ni][1], yacc[mi][ni][2], yacc[mi][ni][3],
                                af[mi][0], af[mi][1], af[mi][2], af[mi][3], b0, b1);
                }
            }
        }
    }

    // Write Y as fp16 (consumed by proj fp16 GEMM) to (B,T,C)
    const int b = bh >> 4;
    const int h = bh & 15;
#pragma unroll
    for (int mi = 0; mi < 2; mi++) {
#pragma unroll
        for (int ni = 0; ni < 4; ni++) {
            const int t0 = q0 + wm + mi * 16 + g;
            const int t1 = t0 + 8;
            const int d = wn + ni * 8 + 2 * t4;
            *(half2*)&g_yh[((size_t)(b * T_ + t0)) * C_ + h * HD + d] =
                __floats2half2_rn(yacc[mi][ni][0], yacc[mi][ni][1]);
            *(half2*)&g_yh[((size_t)(b * T_ + t1)) * C_ + h * HD + d] =
                __floats2half2_rn(yacc[mi][ni][2], yacc[mi][ni][3]);
        }
    }
}

// ---------------------------------------------------------------------------
extern "C" void kernel_launch(void* const* d_in, const int* in_sizes, int n_in,
                              void* d_out, int out_size) {
    (void)in_sizes; (void)n_in; (void)out_size;
    const float* x      = (const float*)d_in[0];
    const float* W_attn = (const float*)d_in[1];
    const float* b_attn = (const float*)d_in[2];
    const float* W_proj = (const float*)d_in[3];
    const float* b_proj = (const float*)d_in[4];
    float* out = (float*)d_out;

    cudaFuncSetAttribute(gemm_f16<0>, cudaFuncAttributeMaxDynamicSharedMemorySize, GEMM_SMEM);
    cudaFuncSetAttribute(gemm_f16<1>, cudaFuncAttributeMaxDynamicSharedMemorySize, GEMM_SMEM);
    cudaFuncSetAttribute(attn_f16, cudaFuncAttributeMaxDynamicSharedMemorySize, ATTN_SMEM);

    // Prep: round x, transpose weights (destinations selected in device code)
    round_x<<<(M_ROWS * C_ / 4 + 255) / 256, 256>>>(x);
    transpose_half<0><<<dim3(N_QKV / 32, C_ / 32), dim3(32, 8)>>>(W_attn, C_, N_QKV);
    transpose_half<1><<<dim3(C_ / 32, C_ / 32), dim3(32, 8)>>>(W_proj, C_, C_);

    dim3 g1(N_QKV / 128, M_ROWS / 128);
    gemm_f16<0><<<g1, 256, GEMM_SMEM>>>(b_attn, nullptr, M_ROWS, N_QKV, C_);

    q2k2_kernel<<<(BH * T_ + 255) / 256, 256>>>();

    attn_f16<<<dim3(T_ / 128, BH), 256, ATTN_SMEM>>>();

    dim3 g2(C_ / 128, M_ROWS / 128);
    gemm_f16<1><<<g2, 256, GEMM_SMEM>>>(b_proj, out, M_ROWS, C_, C_);
}

// round 10
// speedup vs baseline: 5.6783x; 1.0352x over previous
#include <cuda_runtime.h>
#include <cuda_fp16.h>
#include <cstdint>

// Problem constants
constexpr int B_ = 4;
constexpr int T_ = 2048;
constexpr int C_ = 1024;
constexpr int H_ = 16;
constexpr int HD = 64;
constexpr int BH = B_ * H_;     // 64
constexpr int M_ROWS = B_ * T_; // 8192
constexpr int N_QKV = 3 * C_;   // 3072

constexpr float SCALE = -1.0f / 16.0f; // -1/(2*sqrt(64))

// Device scratch (no cudaMalloc). Device globals only referenced in device code.
__device__ __half g_qh[BH * T_ * HD];   // q fp16 [bh][t][d]
__device__ __half g_kh[BH * T_ * HD];   // k fp16 [bh][t][d]
__device__ __half g_vt[BH * HD * T_];   // v fp16 TRANSPOSED [bh][d][t]
__device__ __half g_yh[M_ROWS * C_];    // attention output, fp16 [m][c]
__device__ __half g_xh[M_ROWS * C_];    // x rounded to fp16 [m][k]
__device__ __half g_wat[N_QKV * C_];    // W_attn^T fp16 [n][k]
__device__ __half g_wpt[C_ * C_];       // W_proj^T fp16 [n][k]
__device__ float g_q2[BH * T_];
__device__ float g_k2[BH * T_];

__device__ __forceinline__ void mma_f16(float& c0, float& c1, float& c2, float& c3,
                                        uint32_t a0, uint32_t a1, uint32_t a2, uint32_t a3,
                                        uint32_t b0, uint32_t b1) {
    asm volatile(
        "mma.sync.aligned.m16n8k16.row.col.f32.f16.f16.f32 "
        "{%0,%1,%2,%3}, {%4,%5,%6,%7}, {%8,%9}, {%0,%1,%2,%3};"
        : "+f"(c0), "+f"(c1), "+f"(c2), "+f"(c3)
        : "r"(a0), "r"(a1), "r"(a2), "r"(a3), "r"(b0), "r"(b1));
}

__device__ __forceinline__ void ldsm_x4(uint32_t& r0, uint32_t& r1,
                                        uint32_t& r2, uint32_t& r3, uint32_t addr) {
    asm volatile("ldmatrix.sync.aligned.m8n8.x4.shared.b16 {%0,%1,%2,%3}, [%4];"
                 : "=r"(r0), "=r"(r1), "=r"(r2), "=r"(r3) : "r"(addr));
}

__device__ __forceinline__ void cp_async16(uint32_t dst, const void* src) {
    asm volatile("cp.async.cg.shared.global [%0], [%1], 16;" :: "r"(dst), "l"(src));
}
__device__ __forceinline__ void cp_commit() {
    asm volatile("cp.async.commit_group;");
}
template <int N>
__device__ __forceinline__ void cp_wait() {
    asm volatile("cp.async.wait_group %0;" :: "n"(N));
}
__device__ __forceinline__ uint32_t smem_u32(const void* p) {
    return (uint32_t)__cvta_generic_to_shared(p);
}

// ---------------------------------------------------------------------------
// Prep: round x to fp16; transpose W matrices to N-major fp16.
// ---------------------------------------------------------------------------
__global__ void round_x(const float* __restrict__ x) {
    size_t i = (size_t)blockIdx.x * blockDim.x + threadIdx.x; // float4 index
    if (i >= (size_t)M_ROWS * C_ / 4) return;
    float4 v = ((const float4*)x)[i];
    ((half2*)g_xh)[i * 2 + 0] = __floats2half2_rn(v.x, v.y);
    ((half2*)g_xh)[i * 2 + 1] = __floats2half2_rn(v.z, v.w);
}

// in: [K][N] fp32 row-major -> out: [N][K] fp16 row-major (dest chosen in device code)
template <int WSEL>
__global__ void transpose_half(const float* __restrict__ in, int K, int N) {
    __half* __restrict__ out = (WSEL == 0) ? g_wat : g_wpt;
    __shared__ float tile[32][33];
    const int n0 = blockIdx.x * 32;
    const int k0 = blockIdx.y * 32;
    const int tx = threadIdx.x;
    const int ty = threadIdx.y;
#pragma unroll
    for (int j = 0; j < 4; j++)
        tile[ty + j * 8][tx] = in[(size_t)(k0 + ty + j * 8) * N + n0 + tx];
    __syncthreads();
#pragma unroll
    for (int j = 0; j < 4; j++)
        out[(size_t)(n0 + ty + j * 8) * K + k0 + tx] =
            __float2half_rn(tile[tx][ty + j * 8]);
}

// ---------------------------------------------------------------------------
// Dense fp16 GEMM: C = A(MxK) * B^T stored [N][K] + bias, fp32 accum.
// 128x128x32 tile, 3-stage cp.async, 8 warps (4M x 2N), warp 32x64.
// Fragment loads via ldmatrix.x4 (pitch 40 halves -> conflict-free LDSM).
// ---------------------------------------------------------------------------
constexpr int BKH = 32;  // k per tile (halves)
constexpr int HP = 40;   // halves per row in smem
constexpr int HASZ = 128 * HP;
constexpr int HSTG = 2 * HASZ;
constexpr int GEMM_SMEM = 3 * HSTG * 2;  // bytes (61440)

template <int MODE>
__global__ __launch_bounds__(256) void gemm_f16(
    const float* __restrict__ bias, float* __restrict__ Cout,
    int M, int N, int K)
{
    extern __shared__ __half smh[];

    const __half* __restrict__ A = (MODE == 0) ? g_xh : g_yh;
    const __half* __restrict__ Bt = (MODE == 0) ? g_wat : g_wpt;

    const int tid = threadIdx.x;
    const int lane = tid & 31;
    const int wid = tid >> 5;
    const int g = lane >> 2;
    const int t4 = lane & 3;
    const int wm = (wid & 3) * 32;
    const int wn = (wid >> 2) * 64;
    const int m0 = blockIdx.y * 128;
    const int n0 = blockIdx.x * 128;
    const int lrow = lane & 15;          // ldmatrix row within m16/n16 group
    const int lk = (lane >> 4) * 8;      // ldmatrix k-half select

    const int nt = K / BKH;

    auto issue = [&](int stage, int k0) {
        __half* sA = smh + stage * HSTG;
        __half* sB = sA + HASZ;
#pragma unroll
        for (int h = 0; h < 2; h++) {
            int c = tid + h * 256;
            int row = c >> 2, c8 = (c & 3) * 8;
            cp_async16(smem_u32(&sA[row * HP + c8]), &A[(size_t)(m0 + row) * K + k0 + c8]);
            cp_async16(smem_u32(&sB[row * HP + c8]), &Bt[(size_t)(n0 + row) * K + k0 + c8]);
        }
        cp_commit();
    };

    float acc[2][8][4] = {};

    issue(0, 0);
    issue(1, BKH);

    for (int i = 0; i < nt; i++) {
        // Outstanding groups before wait: {i, i+1} for i<=nt-2, only {i} at tail.
        if (i == nt - 1) cp_wait<0>(); else cp_wait<1>();
        __syncthreads();
        if (i + 2 < nt) issue((i + 2) % 3, (i + 2) * BKH);

        const __half* sA = smh + (i % 3) * HSTG;
        const __half* sB = sA + HASZ;

#pragma unroll
        for (int kk = 0; kk < BKH; kk += 16) {
            uint32_t af[2][4];
#pragma unroll
            for (int mi = 0; mi < 2; mi++)
                ldsm_x4(af[mi][0], af[mi][1], af[mi][2], af[mi][3],
                        smem_u32(&sA[(wm + mi * 16 + lrow) * HP + kk + lk]));
            uint32_t bf[8][2];
#pragma unroll
            for (int nj = 0; nj < 4; nj++)
                ldsm_x4(bf[2 * nj][0], bf[2 * nj + 1][0], bf[2 * nj][1], bf[2 * nj + 1][1],
                        smem_u32(&sB[(wn + nj * 16 + lrow) * HP + kk + lk]));
#pragma unroll
            for (int mi = 0; mi < 2; mi++)
#pragma unroll
                for (int ni = 0; ni < 8; ni++)
                    mma_f16(acc[mi][ni][0], acc[mi][ni][1], acc[mi][ni][2], acc[mi][ni][3],
                            af[mi][0], af[mi][1], af[mi][2], af[mi][3],
                            bf[ni][0], bf[ni][1]);
        }
    }

    // Epilogue
#pragma unroll
    for (int mi = 0; mi < 2; mi++) {
#pragma unroll
        for (int ni = 0; ni < 8; ni++) {
            const int r0 = m0 + wm + mi * 16 + g;
            const int r1 = r0 + 8;
            const int c0 = n0 + wn + ni * 8 + 2 * t4;
            const float bia = bias[c0];
            const float bib = bias[c0 + 1];
            float v00 = acc[mi][ni][0] + bia;
            float v01 = acc[mi][ni][1] + bib;
            float v10 = acc[mi][ni][2] + bia;
            float v11 = acc[mi][ni][3] + bib;
            if (MODE == 0) {
#pragma unroll
                for (int e = 0; e < 4; e++) {
                    const int m = (e < 2) ? r0 : r1;
                    const int n = c0 + (e & 1);
                    const float v = (e == 0) ? v00 : (e == 1) ? v01 : (e == 2) ? v10 : v11;
                    const int part = n >> 10;
                    const int cc = n & 1023;
                    const int h = cc >> 6;
                    const int d = cc & 63;
                    const int b = m >> 11;
                    const int t = m & 2047;
                    const int bh = b * H_ + h;
                    const __half hv = __float2half_rn(v);
                    if (part == 0)
                        g_qh[((size_t)bh * T_ + t) * HD + d] = hv;
                    else if (part == 1)
                        g_kh[((size_t)bh * T_ + t) * HD + d] = hv;
                    else
                        g_vt[((size_t)bh * HD + d) * T_ + t] = hv; // transposed
                }
            } else {
                *(float2*)&Cout[(size_t)r0 * N + c0] = make_float2(v00, v01);
                *(float2*)&Cout[(size_t)r1 * N + c0] = make_float2(v10, v11);
            }
        }
    }
}

// ---------------------------------------------------------------------------
// Row squared norms of q and k from the fp16-rounded values
// ---------------------------------------------------------------------------
__global__ void q2k2_kernel() {
    const int idx = blockIdx.x * blockDim.x + threadIdx.x;
    if (idx >= BH * T_) return;
    const half2* q = (const half2*)(g_qh + (size_t)idx * HD);
    const half2* k = (const half2*)(g_kh + (size_t)idx * HD);
    float sq = 0.0f, sk = 0.0f;
#pragma unroll
    for (int i = 0; i < HD / 2; i++) {
        float2 a = __half22float2(q[i]);
        sq += a.x * a.x + a.y * a.y;
        float2 b = __half22float2(k[i]);
        sk += b.x * b.x + b.y * b.y;
    }
    g_q2[idx] = sq;
    g_k2[idx] = sk;
}

// ---------------------------------------------------------------------------
// Streaming causal Gaussian attention, fp16 mma + ldmatrix, 2-stage cp.async.
// Block = 128-row q-tile x bh. 8 warps (4 M x 2 N), warp tile 32x32.
// Smem 72 KB -> 2 CTAs/SM. Pitch 72 halves -> conflict-free LDSM.
// ---------------------------------------------------------------------------
constexpr int QP = 72; // halves per row
constexpr int Q_OFF = 0;
constexpr int S_OFF = 128 * QP;
constexpr int K_OFF = S_OFF + 128 * QP;
constexpr int V_OFF = K_OFF + 2 * 64 * QP;
constexpr int ATTN_SMEM = (V_OFF + 2 * 64 * QP) * 2; // bytes

__global__ __launch_bounds__(256) void attn_f16() {
    extern __shared__ __half smh[];
    __half* Qs = smh + Q_OFF;
    __half* Ss = smh + S_OFF;

    const int bh = blockIdx.y;
    const int qt = (int)gridDim.x - 1 - (int)blockIdx.x; // longest blocks first
    const int q0 = qt * 128;
    const int tid = threadIdx.x;
    const int lane = tid & 31;
    const int wid = tid >> 5;
    const int g = lane >> 2;
    const int t4 = lane & 3;
    const int wm = (wid & 3) * 32;   // q rows
    const int wn = (wid >> 2) * 32;  // k cols / d cols
    const int lrow = lane & 15;
    const int lk = (lane >> 4) * 8;

    const __half* __restrict__ qp = g_qh + (size_t)bh * T_ * HD;
    const __half* __restrict__ kp = g_kh + (size_t)bh * T_ * HD;
    const __half* __restrict__ vtp = g_vt + (size_t)bh * HD * T_;

    auto issueKV = [&](int stage, int k0) {
        __half* Ks = smh + K_OFF + stage * 64 * QP;
        __half* Vs = smh + V_OFF + stage * 64 * QP;
#pragma unroll
        for (int h2 = 0; h2 < 2; h2++) {
            int c = tid + h2 * 256;
            int row = c >> 3, cc = (c & 7) * 8;
            cp_async16(smem_u32(&Ks[row * QP + cc]), &kp[(size_t)(k0 + row) * HD + cc]);
            cp_async16(smem_u32(&Vs[row * QP + cc]), &vtp[(size_t)row * T_ + k0 + cc]);
        }
        cp_commit();
    };

    {
#pragma unroll
        for (int h2 = 0; h2 < 4; h2++) {
            int c = tid + h2 * 256;
            int row = c >> 3, cc = (c & 7) * 8;
            cp_async16(smem_u32(&Qs[row * QP + cc]), &qp[(size_t)(q0 + row) * HD + cc]);
        }
        issueKV(0, 0);
    }

    float q2v[4];
#pragma unroll
    for (int mi = 0; mi < 2; mi++) {
        q2v[mi * 2 + 0] = g_q2[bh * T_ + q0 + wm + mi * 16 + g];
        q2v[mi * 2 + 1] = g_q2[bh * T_ + q0 + wm + mi * 16 + g + 8];
    }

    float yacc[2][4][4] = {};

    const int ntile = 2 * qt + 2;

    for (int jt = 0; jt < ntile; jt++) {
        const int st = jt & 1;
        const int k0 = jt * 64;
        cp_wait<0>();
        __syncthreads();
        if (jt + 1 < ntile) issueKV(st ^ 1, (jt + 1) * 64);

        const bool full_mask = (k0 > q0 + wm + 31);

        const __half* Ks = smh + K_OFF + st * 64 * QP;
        const __half* Vs = smh + V_OFF + st * 64 * QP;

        if (!full_mask) {
            float2 k2c[4];
#pragma unroll
            for (int ni = 0; ni < 4; ni++)
                k2c[ni] = *(const float2*)&g_k2[bh * T_ + k0 + wn + ni * 8 + 2 * t4];

            float sacc[2][4][4] = {};
#pragma unroll
            for (int kk = 0; kk < 64; kk += 16) {
                uint32_t af[2][4];
#pragma unroll
                for (int mi = 0; mi < 2; mi++)
                    ldsm_x4(af[mi][0], af[mi][1], af[mi][2], af[mi][3],
                            smem_u32(&Qs[(wm + mi * 16 + lrow) * QP + kk + lk]));
                uint32_t bf[4][2];
#pragma unroll
                for (int nj = 0; nj < 2; nj++)
                    ldsm_x4(bf[2 * nj][0], bf[2 * nj + 1][0], bf[2 * nj][1], bf[2 * nj + 1][1],
                            smem_u32(&Ks[(wn + nj * 16 + lrow) * QP + kk + lk]));
#pragma unroll
                for (int ni = 0; ni < 4; ni++)
#pragma unroll
                    for (int mi = 0; mi < 2; mi++)
                        mma_f16(sacc[mi][ni][0], sacc[mi][ni][1], sacc[mi][ni][2], sacc[mi][ni][3],
                                af[mi][0], af[mi][1], af[mi][2], af[mi][3],
                                bf[ni][0], bf[ni][1]);
            }

#pragma unroll
            for (int mi = 0; mi < 2; mi++) {
#pragma unroll
                for (int ni = 0; ni < 4; ni++) {
                    const int r0l = wm + mi * 16 + g;
                    const int r1l = r0l + 8;
                    const int tq0 = q0 + r0l;
                    const int tq1 = q0 + r1l;
                    const int c0l = wn + ni * 8 + 2 * t4;
                    const int tk0 = k0 + c0l;
                    const int tk1 = tk0 + 1;
                    const float k2a = k2c[ni].x;
                    const float k2b = k2c[ni].y;
                    const float q2a = q2v[mi * 2 + 0];
                    const float q2b = q2v[mi * 2 + 1];
                    float e00 = __expf((q2a + k2a - 2.0f * sacc[mi][ni][0]) * SCALE);
                    float e01 = __expf((q2a + k2b - 2.0f * sacc[mi][ni][1]) * SCALE);
                    float e10 = __expf((q2b + k2a - 2.0f * sacc[mi][ni][2]) * SCALE);
                    float e11 = __expf((q2b + k2b - 2.0f * sacc[mi][ni][3]) * SCALE);
                    if (tk0 > tq0) e00 = 0.0f;
                    if (tk1 > tq0) e01 = 0.0f;
                    if (tk0 > tq1) e10 = 0.0f;
                    if (tk1 > tq1) e11 = 0.0f;
                    *(half2*)&Ss[r0l * QP + c0l] = __floats2half2_rn(e00, e01);
                    *(half2*)&Ss[r1l * QP + c0l] = __floats2half2_rn(e10, e11);
                }
            }
        }
        __syncthreads();

        if (!full_mask) {
#pragma unroll
            for (int kk = 0; kk < 64; kk += 16) {
                uint32_t af[2][4];
#pragma unroll
                for (int mi = 0; mi < 2; mi++)
                    ldsm_x4(af[mi][0], af[mi][1], af[mi][2], af[mi][3],
                            smem_u32(&Ss[(wm + mi * 16 + lrow) * QP + kk + lk]));
                uint32_t bf[4][2];
#pragma unroll
                for (int nj = 0; nj < 2; nj++)
                    ldsm_x4(bf[2 * nj][0], bf[2 * nj + 1][0], bf[2 * nj][1], bf[2 * nj + 1][1],
                            smem_u32(&Vs[(wn + nj * 16 + lrow) * QP + kk + lk]));
#pragma unroll
                for (int ni = 0; ni < 4; ni++)
#pragma unroll
                    for (int mi = 0; mi < 2; mi++)
                        mma_f16(yacc[mi][ni][0], yacc[mi][ni][1], yacc[mi][ni][2], yacc[mi][ni][3],
                                af[mi][0], af[mi][1], af[mi][2], af[mi][3],
                                bf[ni][0], bf[ni][1]);
            }
        }
    }

    // Write Y as fp16 (consumed by proj fp16 GEMM) to (B,T,C)
    const int b = bh >> 4;
    const int h = bh & 15;
#pragma unroll
    for (int mi = 0; mi < 2; mi++) {
#pragma unroll
        for (int ni = 0; ni < 4; ni++) {
            const int t0 = q0 + wm + mi * 16 + g;
            const int t1 = t0 + 8;
            const int d = wn + ni * 8 + 2 * t4;
            *(half2*)&g_yh[((size_t)(b * T_ + t0)) * C_ + h * HD + d] =
                __floats2half2_rn(yacc[mi][ni][0], yacc[mi][ni][1]);
            *(half2*)&g_yh[((size_t)(b * T_ + t1)) * C_ + h * HD + d] =
                __floats2half2_rn(yacc[mi][ni][2], yacc[mi][ni][3]);
        }
    }
}

// ---------------------------------------------------------------------------
extern "C" void kernel_launch(void* const* d_in, const int* in_sizes, int n_in,
                              void* d_out, int out_size) {
    (void)in_sizes; (void)n_in; (void)out_size;
    const float* x      = (const float*)d_in[0];
    const float* W_attn = (const float*)d_in[1];
    const float* b_attn = (const float*)d_in[2];
    const float* W_proj = (const float*)d_in[3];
    const float* b_proj = (const float*)d_in[4];
    float* out = (float*)d_out;

    cudaFuncSetAttribute(gemm_f16<0>, cudaFuncAttributeMaxDynamicSharedMemorySize, GEMM_SMEM);
    cudaFuncSetAttribute(gemm_f16<1>, cudaFuncAttributeMaxDynamicSharedMemorySize, GEMM_SMEM);
    cudaFuncSetAttribute(attn_f16, cudaFuncAttributeMaxDynamicSharedMemorySize, ATTN_SMEM);

    round_x<<<(M_ROWS * C_ / 4 + 255) / 256, 256>>>(x);
    transpose_half<0><<<dim3(N_QKV / 32, C_ / 32), dim3(32, 8)>>>(W_attn, C_, N_QKV);
    transpose_half<1><<<dim3(C_ / 32, C_ / 32), dim3(32, 8)>>>(W_proj, C_, C_);

    dim3 g1(N_QKV / 128, M_ROWS / 128);
    gemm_f16<0><<<g1, 256, GEMM_SMEM>>>(b_attn, nullptr, M_ROWS, N_QKV, C_);

    q2k2_kernel<<<(BH * T_ + 255) / 256, 256>>>();

    attn_f16<<<dim3(T_ / 128, BH), 256, ATTN_SMEM>>>();

    dim3 g2(C_ / 128, M_ROWS / 128);
    gemm_f16<1><<<g2, 256, GEMM_SMEM>>>(b_proj, out, M_ROWS, C_, C_);
}

// round 11
// speedup vs baseline: 6.1444x; 1.0821x over previous
#include <cuda_runtime.h>
#include <cuda_fp16.h>
#include <cstdint>

// Problem constants
constexpr int B_ = 4;
constexpr int T_ = 2048;
constexpr int C_ = 1024;
constexpr int H_ = 16;
constexpr int HD = 64;
constexpr int BH = B_ * H_;     // 64
constexpr int M_ROWS = B_ * T_; // 8192
constexpr int N_QKV = 3 * C_;   // 3072

constexpr float SCALE = -1.0f / 16.0f; // -1/(2*sqrt(64))

// Device scratch (no cudaMalloc). Device globals only referenced in device code.
__device__ __half g_qh[BH * T_ * HD];   // q fp16 [bh][t][d]
__device__ __half g_kh[BH * T_ * HD];   // k fp16 [bh][t][d]
__device__ __half g_vt[BH * HD * T_];   // v fp16 TRANSPOSED [bh][d][t]
__device__ __half g_yh[M_ROWS * C_];    // attention output, fp16 [m][c]
__device__ __half g_xh[M_ROWS * C_];    // x rounded to fp16 [m][k]
__device__ __half g_wat[N_QKV * C_];    // W_attn^T fp16 [n][k]
__device__ __half g_wpt[C_ * C_];       // W_proj^T fp16 [n][k]
__device__ float g_q2[BH * T_];
__device__ float g_k2[BH * T_];

__device__ __forceinline__ void mma_f16(float& c0, float& c1, float& c2, float& c3,
                                        uint32_t a0, uint32_t a1, uint32_t a2, uint32_t a3,
                                        uint32_t b0, uint32_t b1) {
    asm volatile(
        "mma.sync.aligned.m16n8k16.row.col.f32.f16.f16.f32 "
        "{%0,%1,%2,%3}, {%4,%5,%6,%7}, {%8,%9}, {%0,%1,%2,%3};"
        : "+f"(c0), "+f"(c1), "+f"(c2), "+f"(c3)
        : "r"(a0), "r"(a1), "r"(a2), "r"(a3), "r"(b0), "r"(b1));
}

__device__ __forceinline__ void ldsm_x4(uint32_t& r0, uint32_t& r1,
                                        uint32_t& r2, uint32_t& r3, uint32_t addr) {
    asm volatile("ldmatrix.sync.aligned.m8n8.x4.shared.b16 {%0,%1,%2,%3}, [%4];"
                 : "=r"(r0), "=r"(r1), "=r"(r2), "=r"(r3) : "r"(addr));
}

__device__ __forceinline__ void cp_async16(uint32_t dst, const void* src) {
    asm volatile("cp.async.cg.shared.global [%0], [%1], 16;" :: "r"(dst), "l"(src));
}
__device__ __forceinline__ void cp_commit() {
    asm volatile("cp.async.commit_group;");
}
template <int N>
__device__ __forceinline__ void cp_wait() {
    asm volatile("cp.async.wait_group %0;" :: "n"(N));
}
__device__ __forceinline__ uint32_t smem_u32(const void* p) {
    return (uint32_t)__cvta_generic_to_shared(p);
}

// ---------------------------------------------------------------------------
// Prep: round x to fp16; transpose W matrices to N-major fp16.
// ---------------------------------------------------------------------------
__global__ void round_x(const float* __restrict__ x) {
    size_t i = (size_t)blockIdx.x * blockDim.x + threadIdx.x; // float4 index
    if (i >= (size_t)M_ROWS * C_ / 4) return;
    float4 v = ((const float4*)x)[i];
    ((half2*)g_xh)[i * 2 + 0] = __floats2half2_rn(v.x, v.y);
    ((half2*)g_xh)[i * 2 + 1] = __floats2half2_rn(v.z, v.w);
}

// in: [K][N] fp32 row-major -> out: [N][K] fp16 row-major (dest chosen in device code)
template <int WSEL>
__global__ void transpose_half(const float* __restrict__ in, int K, int N) {
    __half* __restrict__ out = (WSEL == 0) ? g_wat : g_wpt;
    __shared__ float tile[32][33];
    const int n0 = blockIdx.x * 32;
    const int k0 = blockIdx.y * 32;
    const int tx = threadIdx.x;
    const int ty = threadIdx.y;
#pragma unroll
    for (int j = 0; j < 4; j++)
        tile[ty + j * 8][tx] = in[(size_t)(k0 + ty + j * 8) * N + n0 + tx];
    __syncthreads();
#pragma unroll
    for (int j = 0; j < 4; j++)
        out[(size_t)(n0 + ty + j * 8) * K + k0 + tx] =
            __float2half_rn(tile[tx][ty + j * 8]);
}

// ---------------------------------------------------------------------------
// Dense fp16 GEMM: C = A(MxK) * B^T stored [N][K] + bias, fp32 accum.
// 128x128x64 tile, 3-stage cp.async, 8 warps (4M x 2N), warp 32x64.
// ldmatrix.x4 fragment loads (pitch 72 halves -> conflict-free).
// Barriers per k halved vs BKH=32 (16 mainloop iterations for K=1024).
// ---------------------------------------------------------------------------
constexpr int BKH = 64;  // k per tile (halves)
constexpr int HP = 72;   // halves per row in smem
constexpr int HASZ = 128 * HP;           // halves per A (or B) tile
constexpr int HSTG = 2 * HASZ;           // A + B per stage (halves)
constexpr int GEMM_SMEM = 3 * HSTG * 2;  // bytes (110592)

template <int MODE>
__global__ __launch_bounds__(256) void gemm_f16(
    const float* __restrict__ bias, float* __restrict__ Cout,
    int M, int N, int K)
{
    extern __shared__ __half smh[];

    const __half* __restrict__ A = (MODE == 0) ? g_xh : g_yh;
    const __half* __restrict__ Bt = (MODE == 0) ? g_wat : g_wpt;

    const int tid = threadIdx.x;
    const int lane = tid & 31;
    const int wid = tid >> 5;
    const int g = lane >> 2;
    const int t4 = lane & 3;
    const int wm = (wid & 3) * 32;
    const int wn = (wid >> 2) * 64;
    const int m0 = blockIdx.y * 128;
    const int n0 = blockIdx.x * 128;
    const int lrow = lane & 15;          // ldmatrix row within m16/n16 group
    const int lk = (lane >> 4) * 8;      // ldmatrix k-half select

    const int nt = K / BKH;

    auto issue = [&](int stage, int k0) {
        __half* sA = smh + stage * HSTG;
        __half* sB = sA + HASZ;
        // A tile: 128 rows x 64 halves = 1024 16B-chunks, 4/thread; B same.
#pragma unroll
        for (int h = 0; h < 4; h++) {
            int c = tid + h * 256;
            int row = c >> 3, c8 = (c & 7) * 8;
            cp_async16(smem_u32(&sA[row * HP + c8]), &A[(size_t)(m0 + row) * K + k0 + c8]);
            cp_async16(smem_u32(&sB[row * HP + c8]), &Bt[(size_t)(n0 + row) * K + k0 + c8]);
        }
        cp_commit();
    };

    float acc[2][8][4] = {};

    issue(0, 0);
    issue(1, BKH);

    for (int i = 0; i < nt; i++) {
        // Outstanding groups before wait: {i, i+1} for i<=nt-2, only {i} at tail.
        if (i == nt - 1) cp_wait<0>(); else cp_wait<1>();
        __syncthreads();
        if (i + 2 < nt) issue((i + 2) % 3, (i + 2) * BKH);

        const __half* sA = smh + (i % 3) * HSTG;
        const __half* sB = sA + HASZ;

#pragma unroll
        for (int kk = 0; kk < BKH; kk += 16) {
            uint32_t af[2][4];
#pragma unroll
            for (int mi = 0; mi < 2; mi++)
                ldsm_x4(af[mi][0], af[mi][1], af[mi][2], af[mi][3],
                        smem_u32(&sA[(wm + mi * 16 + lrow) * HP + kk + lk]));
            uint32_t bf[8][2];
#pragma unroll
            for (int nj = 0; nj < 4; nj++)
                ldsm_x4(bf[2 * nj][0], bf[2 * nj + 1][0], bf[2 * nj][1], bf[2 * nj + 1][1],
                        smem_u32(&sB[(wn + nj * 16 + lrow) * HP + kk + lk]));
#pragma unroll
            for (int mi = 0; mi < 2; mi++)
#pragma unroll
                for (int ni = 0; ni < 8; ni++)
                    mma_f16(acc[mi][ni][0], acc[mi][ni][1], acc[mi][ni][2], acc[mi][ni][3],
                            af[mi][0], af[mi][1], af[mi][2], af[mi][3],
                            bf[ni][0], bf[ni][1]);
        }
    }

    // Epilogue
#pragma unroll
    for (int mi = 0; mi < 2; mi++) {
#pragma unroll
        for (int ni = 0; ni < 8; ni++) {
            const int r0 = m0 + wm + mi * 16 + g;
            const int r1 = r0 + 8;
            const int c0 = n0 + wn + ni * 8 + 2 * t4;
            const float bia = bias[c0];
            const float bib = bias[c0 + 1];
            float v00 = acc[mi][ni][0] + bia;
            float v01 = acc[mi][ni][1] + bib;
            float v10 = acc[mi][ni][2] + bia;
            float v11 = acc[mi][ni][3] + bib;
            if (MODE == 0) {
#pragma unroll
                for (int e = 0; e < 4; e++) {
                    const int m = (e < 2) ? r0 : r1;
                    const int n = c0 + (e & 1);
                    const float v = (e == 0) ? v00 : (e == 1) ? v01 : (e == 2) ? v10 : v11;
                    const int part = n >> 10;
                    const int cc = n & 1023;
                    const int h = cc >> 6;
                    const int d = cc & 63;
                    const int b = m >> 11;
                    const int t = m & 2047;
                    const int bh = b * H_ + h;
                    const __half hv = __float2half_rn(v);
                    if (part == 0)
                        g_qh[((size_t)bh * T_ + t) * HD + d] = hv;
                    else if (part == 1)
                        g_kh[((size_t)bh * T_ + t) * HD + d] = hv;
                    else
                        g_vt[((size_t)bh * HD + d) * T_ + t] = hv; // transposed
                }
            } else {
                *(float2*)&Cout[(size_t)r0 * N + c0] = make_float2(v00, v01);
                *(float2*)&Cout[(size_t)r1 * N + c0] = make_float2(v10, v11);
            }
        }
    }
}

// ---------------------------------------------------------------------------
// Row squared norms of q and k from the fp16-rounded values
// ---------------------------------------------------------------------------
__global__ void q2k2_kernel() {
    const int idx = blockIdx.x * blockDim.x + threadIdx.x;
    if (idx >= BH * T_) return;
    const half2* q = (const half2*)(g_qh + (size_t)idx * HD);
    const half2* k = (const half2*)(g_kh + (size_t)idx * HD);
    float sq = 0.0f, sk = 0.0f;
#pragma unroll
    for (int i = 0; i < HD / 2; i++) {
        float2 a = __half22float2(q[i]);
        sq += a.x * a.x + a.y * a.y;
        float2 b = __half22float2(k[i]);
        sk += b.x * b.x + b.y * b.y;
    }
    g_q2[idx] = sq;
    g_k2[idx] = sk;
}

// ---------------------------------------------------------------------------
// Streaming causal Gaussian attention, fp16 mma + ldmatrix, 2-stage cp.async.
// Block = 128-row q-tile x bh. 8 warps (4 M x 2 N), warp tile 32x32.
// Post-S sync is a 2-warp NAMED barrier: SV's A-fragments read only S rows
// wm..wm+31 (written by pair {wid, wid+4} covering the 64 columns).
// ---------------------------------------------------------------------------
constexpr int QP = 72; // halves per row
constexpr int Q_OFF = 0;
constexpr int S_OFF = 128 * QP;
constexpr int K_OFF = S_OFF + 128 * QP;
constexpr int V_OFF = K_OFF + 2 * 64 * QP;
constexpr int ATTN_SMEM = (V_OFF + 2 * 64 * QP) * 2; // bytes

__global__ __launch_bounds__(256) void attn_f16() {
    extern __shared__ __half smh[];
    __half* Qs = smh + Q_OFF;
    __half* Ss = smh + S_OFF;

    const int bh = blockIdx.y;
    const int qt = (int)gridDim.x - 1 - (int)blockIdx.x; // longest blocks first
    const int q0 = qt * 128;
    const int tid = threadIdx.x;
    const int lane = tid & 31;
    const int wid = tid >> 5;
    const int g = lane >> 2;
    const int t4 = lane & 3;
    const int wm = (wid & 3) * 32;   // q rows
    const int wn = (wid >> 2) * 32;  // k cols / d cols
    const int lrow = lane & 15;
    const int lk = (lane >> 4) * 8;
    const int pair_bar = 1 + (wid & 3); // named barrier id for the wm row-band

    const __half* __restrict__ qp = g_qh + (size_t)bh * T_ * HD;
    const __half* __restrict__ kp = g_kh + (size_t)bh * T_ * HD;
    const __half* __restrict__ vtp = g_vt + (size_t)bh * HD * T_;

    auto issueKV = [&](int stage, int k0) {
        __half* Ks = smh + K_OFF + stage * 64 * QP;
        __half* Vs = smh + V_OFF + stage * 64 * QP;
#pragma unroll
        for (int h2 = 0; h2 < 2; h2++) {
            int c = tid + h2 * 256;
            int row = c >> 3, cc = (c & 7) * 8;
            cp_async16(smem_u32(&Ks[row * QP + cc]), &kp[(size_t)(k0 + row) * HD + cc]);
            cp_async16(smem_u32(&Vs[row * QP + cc]), &vtp[(size_t)row * T_ + k0 + cc]);
        }
        cp_commit();
    };

    {
#pragma unroll
        for (int h2 = 0; h2 < 4; h2++) {
            int c = tid + h2 * 256;
            int row = c >> 3, cc = (c & 7) * 8;
            cp_async16(smem_u32(&Qs[row * QP + cc]), &qp[(size_t)(q0 + row) * HD + cc]);
        }
        issueKV(0, 0);
    }

    float q2v[4];
#pragma unroll
    for (int mi = 0; mi < 2; mi++) {
        q2v[mi * 2 + 0] = g_q2[bh * T_ + q0 + wm + mi * 16 + g];
        q2v[mi * 2 + 1] = g_q2[bh * T_ + q0 + wm + mi * 16 + g + 8];
    }

    float yacc[2][4][4] = {};

    const int ntile = 2 * qt + 2;

    for (int jt = 0; jt < ntile; jt++) {
        const int st = jt & 1;
        const int k0 = jt * 64;
        cp_wait<0>();
        __syncthreads();   // K/V stage ready; all warps done with prev tile's SV
        if (jt + 1 < ntile) issueKV(st ^ 1, (jt + 1) * 64);

        const bool full_mask = (k0 > q0 + wm + 31);

        const __half* Ks = smh + K_OFF + st * 64 * QP;
        const __half* Vs = smh + V_OFF + st * 64 * QP;

        if (!full_mask) {
            float2 k2c[4];
#pragma unroll
            for (int ni = 0; ni < 4; ni++)
                k2c[ni] = *(const float2*)&g_k2[bh * T_ + k0 + wn + ni * 8 + 2 * t4];

            float sacc[2][4][4] = {};
#pragma unroll
            for (int kk = 0; kk < 64; kk += 16) {
                uint32_t af[2][4];
#pragma unroll
                for (int mi = 0; mi < 2; mi++)
                    ldsm_x4(af[mi][0], af[mi][1], af[mi][2], af[mi][3],
                            smem_u32(&Qs[(wm + mi * 16 + lrow) * QP + kk + lk]));
                uint32_t bf[4][2];
#pragma unroll
                for (int nj = 0; nj < 2; nj++)
                    ldsm_x4(bf[2 * nj][0], bf[2 * nj + 1][0], bf[2 * nj][1], bf[2 * nj + 1][1],
                            smem_u32(&Ks[(wn + nj * 16 + lrow) * QP + kk + lk]));
#pragma unroll
                for (int ni = 0; ni < 4; ni++)
#pragma unroll
                    for (int mi = 0; mi < 2; mi++)
                        mma_f16(sacc[mi][ni][0], sacc[mi][ni][1], sacc[mi][ni][2], sacc[mi][ni][3],
                                af[mi][0], af[mi][1], af[mi][2], af[mi][3],
                                bf[ni][0], bf[ni][1]);
            }

#pragma unroll
            for (int mi = 0; mi < 2; mi++) {
#pragma unroll
                for (int ni = 0; ni < 4; ni++) {
                    const int r0l = wm + mi * 16 + g;
                    const int r1l = r0l + 8;
                    const int tq0 = q0 + r0l;
                    const int tq1 = q0 + r1l;
                    const int c0l = wn + ni * 8 + 2 * t4;
                    const int tk0 = k0 + c0l;
                    const int tk1 = tk0 + 1;
                    const float k2a = k2c[ni].x;
                    const float k2b = k2c[ni].y;
                    const float q2a = q2v[mi * 2 + 0];
                    const float q2b = q2v[mi * 2 + 1];
                    float e00 = __expf((q2a + k2a - 2.0f * sacc[mi][ni][0]) * SCALE);
                    float e01 = __expf((q2a + k2b - 2.0f * sacc[mi][ni][1]) * SCALE);
                    float e10 = __expf((q2b + k2a - 2.0f * sacc[mi][ni][2]) * SCALE);
                    float e11 = __expf((q2b + k2b - 2.0f * sacc[mi][ni][3]) * SCALE);
                    if (tk0 > tq0) e00 = 0.0f;
                    if (tk1 > tq0) e01 = 0.0f;
                    if (tk0 > tq1) e10 = 0.0f;
                    if (tk1 > tq1) e11 = 0.0f;
                    *(half2*)&Ss[r0l * QP + c0l] = __floats2half2_rn(e00, e01);
                    *(half2*)&Ss[r1l * QP + c0l] = __floats2half2_rn(e10, e11);
                }
            }

            // 2-warp named barrier: pair {wid, wid+4} shares this wm row-band
            // (same full_mask predicate), and together wrote all 64 S columns.
            asm volatile("bar.sync %0, 64;" :: "r"(pair_bar) : "memory");

#pragma unroll
            for (int kk = 0; kk < 64; kk += 16) {
                uint32_t af[2][4];
#pragma unroll
                for (int mi = 0; mi < 2; mi++)
                    ldsm_x4(af[mi][0], af[mi][1], af[mi][2], af[mi][3],
                            smem_u32(&Ss[(wm + mi * 16 + lrow) * QP + kk + lk]));
                uint32_t bf[4][2];
#pragma unroll
                for (int nj = 0; nj < 2; nj++)
                    ldsm_x4(bf[2 * nj][0], bf[2 * nj + 1][0], bf[2 * nj][1], bf[2 * nj + 1][1],
                            smem_u32(&Vs[(wn + nj * 16 + lrow) * QP + kk + lk]));
#pragma unroll
                for (int ni = 0; ni < 4; ni++)
#pragma unroll
                    for (int mi = 0; mi < 2; mi++)
                        mma_f16(yacc[mi][ni][0], yacc[mi][ni][1], yacc[mi][ni][2], yacc[mi][ni][3],
                                af[mi][0], af[mi][1], af[mi][2], af[mi][3],
                                bf[ni][0], bf[ni][1]);
            }
        }
    }

    // Write Y as fp16 (consumed by proj fp16 GEMM) to (B,T,C)
    const int b = bh >> 4;
    const int h = bh & 15;
#pragma unroll
    for (int mi = 0; mi < 2; mi++) {
#pragma unroll
        for (int ni = 0; ni < 4; ni++) {
            const int t0 = q0 + wm + mi * 16 + g;
            const int t1 = t0 + 8;
            const int d = wn + ni * 8 + 2 * t4;
            *(half2*)&g_yh[((size_t)(b * T_ + t0)) * C_ + h * HD + d] =
                __floats2half2_rn(yacc[mi][ni][0], yacc[mi][ni][1]);
            *(half2*)&g_yh[((size_t)(b * T_ + t1)) * C_ + h * HD + d] =
                __floats2half2_rn(yacc[mi][ni][2], yacc[mi][ni][3]);
        }
    }
}

// ---------------------------------------------------------------------------
extern "C" void kernel_launch(void* const* d_in, const int* in_sizes, int n_in,
                              void* d_out, int out_size) {
    (void)in_sizes; (void)n_in; (void)out_size;
    const float* x      = (const float*)d_in[0];
    const float* W_attn = (const float*)d_in[1];
    const float* b_attn = (const float*)d_in[2];
    const float* W_proj = (const float*)d_in[3];
    const float* b_proj = (const float*)d_in[4];
    float* out = (float*)d_out;

    cudaFuncSetAttribute(gemm_f16<0>, cudaFuncAttributeMaxDynamicSharedMemorySize, GEMM_SMEM);
    cudaFuncSetAttribute(gemm_f16<1>, cudaFuncAttributeMaxDynamicSharedMemorySize, GEMM_SMEM);
    cudaFuncSetAttribute(attn_f16, cudaFuncAttributeMaxDynamicSharedMemorySize, ATTN_SMEM);

    round_x<<<(M_ROWS * C_ / 4 + 255) / 256, 256>>>(x);
    transpose_half<0><<<dim3(N_QKV / 32, C_ / 32), dim3(32, 8)>>>(W_attn, C_, N_QKV);
    transpose_half<1><<<dim3(C_ / 32, C_ / 32), dim3(32, 8)>>>(W_proj, C_, C_);

    dim3 g1(N_QKV / 128, M_ROWS / 128);
    gemm_f16<0><<<g1, 256, GEMM_SMEM>>>(b_attn, nullptr, M_ROWS, N_QKV, C_);

    q2k2_kernel<<<(BH * T_ + 255) / 256, 256>>>();

    attn_f16<<<dim3(T_ / 128, BH), 256, ATTN_SMEM>>>();

    dim3 g2(C_ / 128, M_ROWS / 128);
    gemm_f16<1><<<g2, 256, GEMM_SMEM>>>(b_proj, out, M_ROWS, C_, C_);
}

// round 14
// speedup vs baseline: 6.7823x; 1.1038x over previous
#include <cuda_runtime.h>
#include <cuda_fp16.h>
#include <cstdint>

// Problem constants
constexpr int B_ = 4;
constexpr int T_ = 2048;
constexpr int C_ = 1024;
constexpr int H_ = 16;
constexpr int HD = 64;
constexpr int BH = B_ * H_;     // 64
constexpr int M_ROWS = B_ * T_; // 8192
constexpr int N_QKV = 3 * C_;   // 3072

constexpr float SCALE = -1.0f / 16.0f; // -1/(2*sqrt(64))

// Device scratch (no cudaMalloc). Device globals only referenced in device code.
__device__ __half g_qh[BH * T_ * HD];   // q fp16 [bh][t][d]
__device__ __half g_kh[BH * T_ * HD];   // k fp16 [bh][t][d]
__device__ __half g_vt[BH * HD * T_];   // v fp16 TRANSPOSED [bh][d][t]
__device__ __half g_yh[M_ROWS * C_];    // attention output, fp16 [m][c]
__device__ __half g_xh[M_ROWS * C_];    // x rounded to fp16 [m][k]
__device__ __half g_wat[N_QKV * C_];    // W_attn^T fp16 [n][k]
__device__ __half g_wpt[C_ * C_];       // W_proj^T fp16 [n][k]
__device__ float g_q2[BH * T_];
__device__ float g_k2[BH * T_];

__device__ __forceinline__ void mma_f16(float& c0, float& c1, float& c2, float& c3,
                                        uint32_t a0, uint32_t a1, uint32_t a2, uint32_t a3,
                                        uint32_t b0, uint32_t b1) {
    asm volatile(
        "mma.sync.aligned.m16n8k16.row.col.f32.f16.f16.f32 "
        "{%0,%1,%2,%3}, {%4,%5,%6,%7}, {%8,%9}, {%0,%1,%2,%3};"
        : "+f"(c0), "+f"(c1), "+f"(c2), "+f"(c3)
        : "r"(a0), "r"(a1), "r"(a2), "r"(a3), "r"(b0), "r"(b1));
}

__device__ __forceinline__ void ldsm_x4(uint32_t& r0, uint32_t& r1,
                                        uint32_t& r2, uint32_t& r3, uint32_t addr) {
    asm volatile("ldmatrix.sync.aligned.m8n8.x4.shared.b16 {%0,%1,%2,%3}, [%4];"
                 : "=r"(r0), "=r"(r1), "=r"(r2), "=r"(r3) : "r"(addr));
}

__device__ __forceinline__ void cp_async16(uint32_t dst, const void* src) {
    asm volatile("cp.async.cg.shared.global [%0], [%1], 16;" :: "r"(dst), "l"(src));
}
__device__ __forceinline__ void cp_commit() {
    asm volatile("cp.async.commit_group;");
}
template <int N>
__device__ __forceinline__ void cp_wait() {
    asm volatile("cp.async.wait_group %0;" :: "n"(N));
}
__device__ __forceinline__ uint32_t smem_u32(const void* p) {
    return (uint32_t)__cvta_generic_to_shared(p);
}
__device__ __forceinline__ uint32_t h2u(half2 h) {
    return *(uint32_t*)&h;
}

// ---------------------------------------------------------------------------
// Prep: round x to fp16; transpose W matrices to N-major fp16.
// ---------------------------------------------------------------------------
__global__ void round_x(const float* __restrict__ x) {
    size_t i = (size_t)blockIdx.x * blockDim.x + threadIdx.x;
    if (i >= (size_t)M_ROWS * C_ / 4) return;
    float4 v = ((const float4*)x)[i];
    ((half2*)g_xh)[i * 2 + 0] = __floats2half2_rn(v.x, v.y);
    ((half2*)g_xh)[i * 2 + 1] = __floats2half2_rn(v.z, v.w);
}

template <int WSEL>
__global__ void transpose_half(const float* __restrict__ in, int K, int N) {
    __half* __restrict__ out = (WSEL == 0) ? g_wat : g_wpt;
    __shared__ float tile[32][33];
    const int n0 = blockIdx.x * 32;
    const int k0 = blockIdx.y * 32;
    const int tx = threadIdx.x;
    const int ty = threadIdx.y;
#pragma unroll
    for (int j = 0; j < 4; j++)
        tile[ty + j * 8][tx] = in[(size_t)(k0 + ty + j * 8) * N + n0 + tx];
    __syncthreads();
#pragma unroll
    for (int j = 0; j < 4; j++)
        out[(size_t)(n0 + ty + j * 8) * K + k0 + tx] =
            __float2half_rn(tile[tx][ty + j * 8]);
}

// ---------------------------------------------------------------------------
// Dense fp16 GEMM: C = A(MxK) * B^T([N][K]) + bias, fp32 accum.
// 128x128x64 tile, 3-stage cp.async, 8 warps (4M x 2N), warp 32x64, ldmatrix.
// MODE 0 additionally reduces per-row |q|^2 / |k|^2 of the stored halves.
// ---------------------------------------------------------------------------
constexpr int BKH = 64;
constexpr int HP = 72;
constexpr int HASZ = 128 * HP;
constexpr int HSTG = 2 * HASZ;
constexpr int GEMM_SMEM = 3 * HSTG * 2;  // 110592 B

template <int MODE>
__global__ __launch_bounds__(256, 2) void gemm_f16(
    const float* __restrict__ bias, float* __restrict__ Cout,
    int M, int N, int K)
{
    extern __shared__ __half smh[];

    const __half* __restrict__ A = (MODE == 0) ? g_xh : g_yh;
    const __half* __restrict__ Bt = (MODE == 0) ? g_wat : g_wpt;

    const int tid = threadIdx.x;
    const int lane = tid & 31;
    const int wid = tid >> 5;
    const int g = lane >> 2;
    const int t4 = lane & 3;
    const int wm = (wid & 3) * 32;
    const int wn = (wid >> 2) * 64;
    const int m0 = blockIdx.y * 128;
    const int n0 = blockIdx.x * 128;
    const int lrow = lane & 15;
    const int lk = (lane >> 4) * 8;

    const int nt = K / BKH;

    auto issue = [&](int stage, int k0) {
        __half* sA = smh + stage * HSTG;
        __half* sB = sA + HASZ;
#pragma unroll
        for (int h = 0; h < 4; h++) {
            int c = tid + h * 256;
            int row = c >> 3, c8 = (c & 7) * 8;
            cp_async16(smem_u32(&sA[row * HP + c8]), &A[(size_t)(m0 + row) * K + k0 + c8]);
            cp_async16(smem_u32(&sB[row * HP + c8]), &Bt[(size_t)(n0 + row) * K + k0 + c8]);
        }
        cp_commit();
    };

    float acc[2][8][4] = {};

    issue(0, 0);
    issue(1, BKH);

    for (int i = 0; i < nt; i++) {
        // Outstanding before wait: {i, i+1} for i<=nt-2, only {i} at tail.
        if (i == nt - 1) cp_wait<0>(); else cp_wait<1>();
        __syncthreads();
        if (i + 2 < nt) issue((i + 2) % 3, (i + 2) * BKH);

        const __half* sA = smh + (i % 3) * HSTG;
        const __half* sB = sA + HASZ;

#pragma unroll
        for (int kk = 0; kk < BKH; kk += 16) {
            uint32_t af[2][4];
#pragma unroll
            for (int mi = 0; mi < 2; mi++)
                ldsm_x4(af[mi][0], af[mi][1], af[mi][2], af[mi][3],
                        smem_u32(&sA[(wm + mi * 16 + lrow) * HP + kk + lk]));
            uint32_t bf[8][2];
#pragma unroll
            for (int nj = 0; nj < 4; nj++)
                ldsm_x4(bf[2 * nj][0], bf[2 * nj + 1][0], bf[2 * nj][1], bf[2 * nj + 1][1],
                        smem_u32(&sB[(wn + nj * 16 + lrow) * HP + kk + lk]));
#pragma unroll
            for (int mi = 0; mi < 2; mi++)
#pragma unroll
                for (int ni = 0; ni < 8; ni++)
                    mma_f16(acc[mi][ni][0], acc[mi][ni][1], acc[mi][ni][2], acc[mi][ni][3],
                            af[mi][0], af[mi][1], af[mi][2], af[mi][3],
                            bf[ni][0], bf[ni][1]);
        }
    }

    // Epilogue (+ fused row-norm reduction for q/k in MODE 0)
    float sq0[2] = {0.0f, 0.0f};
    float sq1[2] = {0.0f, 0.0f};
    const int part = (n0 + wn) >> 10; // constant per warp (64-col head block)

#pragma unroll
    for (int mi = 0; mi < 2; mi++) {
#pragma unroll
        for (int ni = 0; ni < 8; ni++) {
            const int r0 = m0 + wm + mi * 16 + g;
            const int r1 = r0 + 8;
            const int c0 = n0 + wn + ni * 8 + 2 * t4;
            const float bia = bias[c0];
            const float bib = bias[c0 + 1];
            float v00 = acc[mi][ni][0] + bia;
            float v01 = acc[mi][ni][1] + bib;
            float v10 = acc[mi][ni][2] + bia;
            float v11 = acc[mi][ni][3] + bib;
            if (MODE == 0) {
                const __half h00 = __float2half_rn(v00);
                const __half h01 = __float2half_rn(v01);
                const __half h10 = __float2half_rn(v10);
                const __half h11 = __float2half_rn(v11);
                if (part < 2) {
                    float r00 = __half2float(h00), r01 = __half2float(h01);
                    float r10 = __half2float(h10), r11 = __half2float(h11);
                    sq0[mi] += r00 * r00 + r01 * r01;
                    sq1[mi] += r10 * r10 + r11 * r11;
                }
                const int cc = c0 & 1023;
                const int h = cc >> 6;
#pragma unroll
                for (int e = 0; e < 4; e++) {
                    const int m = (e < 2) ? r0 : r1;
                    const int dd = (cc & 63) + (e & 1);
                    const __half hv = (e == 0) ? h00 : (e == 1) ? h01 : (e == 2) ? h10 : h11;
                    const int b = m >> 11;
                    const int t = m & 2047;
                    const int bh = b * H_ + h;
                    if (part == 0)
                        g_qh[((size_t)bh * T_ + t) * HD + dd] = hv;
                    else if (part == 1)
                        g_kh[((size_t)bh * T_ + t) * HD + dd] = hv;
                    else
                        g_vt[((size_t)bh * HD + dd) * T_ + t] = hv;
                }
            } else {
                *(float2*)&Cout[(size_t)r0 * N + c0] = make_float2(v00, v01);
                *(float2*)&Cout[(size_t)r1 * N + c0] = make_float2(v10, v11);
            }
        }
    }

    if (MODE == 0 && part < 2) {
        // quad reduce over t4 (lanes 4g..4g+3)
#pragma unroll
        for (int mi = 0; mi < 2; mi++) {
            float s0 = sq0[mi], s1 = sq1[mi];
            s0 += __shfl_xor_sync(0xffffffffu, s0, 1);
            s0 += __shfl_xor_sync(0xffffffffu, s0, 2);
            s1 += __shfl_xor_sync(0xffffffffu, s1, 1);
            s1 += __shfl_xor_sync(0xffffffffu, s1, 2);
            if (t4 == 0) {
                const int h = ((n0 + wn) & 1023) >> 6;
                float* dst = (part == 0) ? g_q2 : g_k2;
                const int m0r = m0 + wm + mi * 16 + g;
                {
                    const int b = m0r >> 11, t = m0r & 2047;
                    dst[(b * H_ + h) * T_ + t] = s0;
                }
                {
                    const int m1r = m0r + 8;
                    const int b = m1r >> 11, t = m1r & 2047;
                    dst[(b * H_ + h) * T_ + t] = s1;
                }
            }
        }
    }
}

// ---------------------------------------------------------------------------
// Streaming causal Gaussian attention, register-resident S.
// Block = 128-row q-tile x bh. 8 warps, each owns a 16-row band (m16 x n64).
// QK accumulators repacked in registers as SV A-operand (no S smem, no
// intra-tile barrier). 3-stage KV ring, 2 prefetches in flight: at iter jt we
// consume stage jt%3 and issue tile jt+2 into stage (jt+2)%3 (distinct; the
// top-of-loop barrier orders all warps past tile jt-1 which shared it).
// ---------------------------------------------------------------------------
constexpr int QP = 72;
constexpr int Q_OFF = 0;
constexpr int K_OFF = 128 * QP;
constexpr int V_OFF = K_OFF + 3 * 64 * QP;
constexpr int ATTN_SMEM = (V_OFF + 3 * 64 * QP) * 2; // 73728 B

__global__ __launch_bounds__(256, 2) void attn_f16() {
    extern __shared__ __half smh[];
    __half* Qs = smh + Q_OFF;

    const int bh = blockIdx.y;
    const int qt = (int)gridDim.x - 1 - (int)blockIdx.x; // longest blocks first
    const int q0 = qt * 128;
    const int tid = threadIdx.x;
    const int lane = tid & 31;
    const int wid = tid >> 5;
    const int g = lane >> 2;
    const int t4 = lane & 3;
    const int wm = wid * 16;        // q-row band
    const int lrow = lane & 15;
    const int lk = (lane >> 4) * 8;

    const __half* __restrict__ qp = g_qh + (size_t)bh * T_ * HD;
    const __half* __restrict__ kp = g_kh + (size_t)bh * T_ * HD;
    const __half* __restrict__ vtp = g_vt + (size_t)bh * HD * T_;

    const int ntile = 2 * qt + 2;

    auto issueKV = [&](int stage, int k0) {
        __half* Ks = smh + K_OFF + stage * 64 * QP;
        __half* Vs = smh + V_OFF + stage * 64 * QP;
#pragma unroll
        for (int h2 = 0; h2 < 2; h2++) {
            int c = tid + h2 * 256;
            int row = c >> 3, cc = (c & 7) * 8;
            cp_async16(smem_u32(&Ks[row * QP + cc]), &kp[(size_t)(k0 + row) * HD + cc]);
            cp_async16(smem_u32(&Vs[row * QP + cc]), &vtp[(size_t)row * T_ + k0 + cc]);
        }
        cp_commit();
    };

    // Prologue: Q + stage0 as one group; stage1 (ntile >= 2 always).
    {
#pragma unroll
        for (int h2 = 0; h2 < 4; h2++) {
            int c = tid + h2 * 256;
            int row = c >> 3, cc = (c & 7) * 8;
            cp_async16(smem_u32(&Qs[row * QP + cc]), &qp[(size_t)(q0 + row) * HD + cc]);
        }
        issueKV(0, 0);
        issueKV(1, 64);
    }

    const float q2a = g_q2[bh * T_ + q0 + wm + g];
    const float q2b = g_q2[bh * T_ + q0 + wm + g + 8];
    const int tq0 = q0 + wm + g;
    const int tq1 = tq0 + 8;

    float yacc[8][4] = {};

    for (int jt = 0; jt < ntile; jt++) {
        const int st = jt % 3;
        const int k0 = jt * 64;
        // Outstanding before wait: {jt, jt+1} for jt<=ntile-2, only {jt} at tail.
        if (jt == ntile - 1) cp_wait<0>(); else cp_wait<1>();
        __syncthreads(); // all warps done with tile jt-1 (stage (jt+2)%3)
        if (jt + 2 < ntile) issueKV((jt + 2) % 3, (jt + 2) * 64);

        const bool full_mask = (k0 > q0 + wm + 15);
        if (full_mask) continue;

        const __half* Ks = smh + K_OFF + st * 64 * QP;
        const __half* Vs = smh + V_OFF + st * 64 * QP;

        // S = Q.K^T  (warp m16 x n64)
        float sacc[8][4] = {};
#pragma unroll
        for (int kk = 0; kk < 64; kk += 16) {
            uint32_t a0, a1, a2, a3;
            ldsm_x4(a0, a1, a2, a3, smem_u32(&Qs[(wm + lrow) * QP + kk + lk]));
            uint32_t bf[8][2];
#pragma unroll
            for (int nj = 0; nj < 4; nj++)
                ldsm_x4(bf[2 * nj][0], bf[2 * nj + 1][0], bf[2 * nj][1], bf[2 * nj + 1][1],
                        smem_u32(&Ks[(nj * 16 + lrow) * QP + kk + lk]));
#pragma unroll
            for (int j = 0; j < 8; j++)
                mma_f16(sacc[j][0], sacc[j][1], sacc[j][2], sacc[j][3],
                        a0, a1, a2, a3, bf[j][0], bf[j][1]);
        }

        // exp + causal mask -> pack directly into SV A-fragments (registers)
        uint32_t sa[4][4];
#pragma unroll
        for (int j = 0; j < 8; j++) {
            const int c0l = j * 8 + 2 * t4;
            const int tk0 = k0 + c0l;
            const int tk1 = tk0 + 1;
            const float2 k2 = *(const float2*)&g_k2[bh * T_ + tk0];
            float e00 = __expf((q2a + k2.x - 2.0f * sacc[j][0]) * SCALE);
            float e01 = __expf((q2a + k2.y - 2.0f * sacc[j][1]) * SCALE);
            float e10 = __expf((q2b + k2.x - 2.0f * sacc[j][2]) * SCALE);
            float e11 = __expf((q2b + k2.y - 2.0f * sacc[j][3]) * SCALE);
            if (tk0 > tq0) e00 = 0.0f;
            if (tk1 > tq0) e01 = 0.0f;
            if (tk0 > tq1) e10 = 0.0f;
            if (tk1 > tq1) e11 = 0.0f;
            sa[j >> 1][(j & 1) * 2 + 0] = h2u(__floats2half2_rn(e00, e01));
            sa[j >> 1][(j & 1) * 2 + 1] = h2u(__floats2half2_rn(e10, e11));
        }

        // Y += S @ V  (A = register S, B = V^T fragments; k = token)
#pragma unroll
        for (int s = 0; s < 4; s++) {
            uint32_t bf[8][2];
#pragma unroll
            for (int nj = 0; nj < 4; nj++)
                ldsm_x4(bf[2 * nj][0], bf[2 * nj + 1][0], bf[2 * nj][1], bf[2 * nj + 1][1],
                        smem_u32(&Vs[(nj * 16 + lrow) * QP + 16 * s + lk]));
#pragma unroll
            for (int ni = 0; ni < 8; ni++)
                mma_f16(yacc[ni][0], yacc[ni][1], yacc[ni][2], yacc[ni][3],
                        sa[s][0], sa[s][1], sa[s][2], sa[s][3],
                        bf[ni][0], bf[ni][1]);
        }
    }

    // Write Y as fp16 to (B,T,C)
    const int b = bh >> 4;
    const int h = bh & 15;
#pragma unroll
    for (int ni = 0; ni < 8; ni++) {
        const int d = ni * 8 + 2 * t4;
        *(half2*)&g_yh[((size_t)(b * T_ + tq0)) * C_ + h * HD + d] =
            __floats2half2_rn(yacc[ni][0], yacc[ni][1]);
        *(half2*)&g_yh[((size_t)(b * T_ + tq1)) * C_ + h * HD + d] =
            __floats2half2_rn(yacc[ni][2], yacc[ni][3]);
    }
}

// ---------------------------------------------------------------------------
extern "C" void kernel_launch(void* const* d_in, const int* in_sizes, int n_in,
                              void* d_out, int out_size) {
    (void)in_sizes; (void)n_in; (void)out_size;
    const float* x      = (const float*)d_in[0];
    const float* W_attn = (const float*)d_in[1];
    const float* b_attn = (const float*)d_in[2];
    const float* W_proj = (const float*)d_in[3];
    const float* b_proj = (const float*)d_in[4];
    float* out = (float*)d_out;

    cudaFuncSetAttribute(gemm_f16<0>, cudaFuncAttributeMaxDynamicSharedMemorySize, GEMM_SMEM);
    cudaFuncSetAttribute(gemm_f16<1>, cudaFuncAttributeMaxDynamicSharedMemorySize, GEMM_SMEM);
    cudaFuncSetAttribute(attn_f16, cudaFuncAttributeMaxDynamicSharedMemorySize, ATTN_SMEM);

    round_x<<<(M_ROWS * C_ / 4 + 255) / 256, 256>>>(x);
    transpose_half<0><<<dim3(N_QKV / 32, C_ / 32), dim3(32, 8)>>>(W_attn, C_, N_QKV);
    transpose_half<1><<<dim3(C_ / 32, C_ / 32), dim3(32, 8)>>>(W_proj, C_, C_);

    dim3 g1(N_QKV / 128, M_ROWS / 128);
    gemm_f16<0><<<g1, 256, GEMM_SMEM>>>(b_attn, nullptr, M_ROWS, N_QKV, C_);

    attn_f16<<<dim3(T_ / 128, BH), 256, ATTN_SMEM>>>();

    dim3 g2(C_ / 128, M_ROWS / 128);
    gemm_f16<1><<<g2, 256, GEMM_SMEM>>>(b_proj, out, M_ROWS, C_, C_);
}